// round 6
// baseline (speedup 1.0000x reference)
#include <cuda_runtime.h>
#include <cuda_bf16.h>
#include <math.h>
#include <stdint.h>

#define CB 8
#define C2 96
#define H2 112
#define LTOK 12544
#define NWB 2048
#define HID 384

#define SROW 56                 // smem row pitch (halves); 112B = 16*7 -> aligned + conflict-free
#define A_H (128*SROW)
#define B_H (96*SROW)
#define SMEM_BYTES ((2*(A_H+B_H))*2)

// weight arena offsets (elements)
#define OFF_WC   0
#define OFF_QKV  294912
#define OFF_PROJ 350208
#define OFF_F1   368640
#define OFF_F2   442368
#define OFF_OUT  516096
#define TOTW     520704

__device__ float d_bufX[CB*LTOK*C2];            // residual stream (float)
__device__ float d_bufQ[NWB*3*6*49*16];         // qkv head-split (float)
__device__ __nv_bfloat16 d_bWh[CB*LTOK*C2], d_bWl[CB*LTOK*C2];   // LN out planes
__device__ __nv_bfloat16 d_bAh[CB*LTOK*C2], d_bAl[CB*LTOK*C2];   // attn out planes
__device__ __nv_bfloat16 d_bHh[CB*LTOK*HID], d_bHl[CB*LTOK*HID]; // gelu out planes
__device__ __nv_bfloat16 d_wh[TOTW], d_wl[TOTW];                 // weight planes
__device__ float d_cscale[96];
__device__ float d_cshift[96];

// ---------------- helpers ----------------
__device__ __forceinline__ uint32_t smem_u32(const void* p) {
    uint32_t a;
    asm("{ .reg .u64 t; cvta.to.shared.u64 t, %1; cvt.u32.u64 %0, t; }" : "=r"(a) : "l"(p));
    return a;
}
__device__ __forceinline__ void ldm_x4(uint32_t* r, uint32_t addr) {
    asm volatile("ldmatrix.sync.aligned.m8n8.x4.shared.b16 {%0,%1,%2,%3}, [%4];"
        : "=r"(r[0]), "=r"(r[1]), "=r"(r[2]), "=r"(r[3]) : "r"(addr));
}
__device__ __forceinline__ void ldm_x2(uint32_t* r, uint32_t addr) {
    asm volatile("ldmatrix.sync.aligned.m8n8.x2.shared.b16 {%0,%1}, [%2];"
        : "=r"(r[0]), "=r"(r[1]) : "r"(addr));
}
__device__ __forceinline__ void mma_bf16(float* c, const uint32_t* a, const uint32_t* b) {
    asm volatile("mma.sync.aligned.m16n8k16.row.col.f32.bf16.bf16.f32 "
        "{%0,%1,%2,%3}, {%4,%5,%6,%7}, {%8,%9}, {%0,%1,%2,%3};"
        : "+f"(c[0]), "+f"(c[1]), "+f"(c[2]), "+f"(c[3])
        : "r"(a[0]), "r"(a[1]), "r"(a[2]), "r"(a[3]), "r"(b[0]), "r"(b[1]));
}
__device__ __forceinline__ void split1(float x, __nv_bfloat16& h, __nv_bfloat16& l) {
    h = __float2bfloat16_rn(x);
    l = __float2bfloat16_rn(x - __bfloat162float(h));
}
__device__ __forceinline__ void split2(float x, float y, uint32_t& h, uint32_t& l) {
    __nv_bfloat16 hx, lx, hy, ly;
    split1(x, hx, lx); split1(y, hy, ly);
    h = ((uint32_t)__bfloat16_as_ushort(hy) << 16) | (uint32_t)__bfloat16_as_ushort(hx);
    l = ((uint32_t)__bfloat16_as_ushort(ly) << 16) | (uint32_t)__bfloat16_as_ushort(lx);
}
__device__ __forceinline__ void split4(float4 a, uint2& h, uint2& l) {
    split2(a.x, a.y, h.x, l.x);
    split2(a.z, a.w, h.y, l.y);
}

// ---------------- prep kernels ----------------
__global__ void prep_conv(const float* __restrict__ up_w, const float* __restrict__ up_b,
                          const float* __restrict__ bn_g, const float* __restrict__ bn_b,
                          const float* __restrict__ bn_m, const float* __restrict__ bn_v) {
    int tid = blockIdx.x * blockDim.x + threadIdx.x;
    if (tid < 96) {
        float s = bn_g[tid] * rsqrtf(bn_v[tid] + 1e-5f);
        d_cscale[tid] = s;
        d_cshift[tid] = (up_b[tid] - bn_m[tid]) * s + bn_b[tid];
    }
    int total = 4 * 96 * 192;
    for (int idx = tid; idx < total; idx += gridDim.x * blockDim.x) {
        int p  = idx / (96 * 192);
        int r  = idx % (96 * 192);
        int co = r / 192, ci = r % 192;
        int py = p >> 1, px = p & 1;
        const float* w = up_w + ((size_t)co * 192 + ci) * 9;
        float cs[3][2];
        #pragma unroll
        for (int ky = 0; ky < 3; ky++) {
            float w0 = w[ky*3], w1 = w[ky*3+1], w2 = w[ky*3+2];
            cs[ky][0] = (px == 0) ? w0 : (w0 + w1);
            cs[ky][1] = (px == 0) ? (w1 + w2) : w2;
        }
        size_t dst = (size_t)OFF_WC + ((size_t)p * 96 + co) * 768 + ci * 4;
        float v[4];
        #pragma unroll
        for (int b2 = 0; b2 < 2; b2++) {
            v[b2]     = (py == 0) ? cs[0][b2] : (cs[0][b2] + cs[1][b2]);
            v[2 + b2] = (py == 0) ? (cs[1][b2] + cs[2][b2]) : cs[2][b2];
        }
        #pragma unroll
        for (int j = 0; j < 4; j++) {
            __nv_bfloat16 h, l;
            split1(v[j], h, l);
            d_wh[dst + j] = h; d_wl[dst + j] = l;
        }
    }
}

__global__ void prep_w(const float* __restrict__ qkvw, const float* __restrict__ projw,
                       const float* __restrict__ f1w,  const float* __restrict__ f2w,
                       const float* __restrict__ outw) {
    int tid = blockIdx.x * blockDim.x + threadIdx.x;
    int total = TOTW - OFF_QKV;
    for (int idx = tid; idx < total; idx += gridDim.x * blockDim.x) {
        float v; size_t dst = OFF_QKV + idx;
        int r = idx;
        if (r < 55296)               v = qkvw[r];
        else if ((r -= 55296) < 18432) v = projw[r];
        else if ((r -= 18432) < 73728) v = f1w[r];
        else if ((r -= 73728) < 73728) v = f2w[r];
        else                           v = outw[r - 73728];
        __nv_bfloat16 h, l;
        split1(v, h, l);
        d_wh[dst] = h; d_wl[dst] = l;
    }
}

// ---------------- A loaders (float path: conv gather / direct) ---------------
struct ALDirect {
    const float* A; int K;
    struct Ctx { const float* p; };
    __device__ Ctx prep(int m) const { Ctx c; c.p = A + (size_t)m * K; return c; }
    __device__ float4 load(const Ctx& c, int k) const { return *(const float4*)(c.p + k); }
};
struct ALConv {
    const float* in; int py, px;
    struct Ctx { const float* base; int o0, o1, o2, o3; };
    __device__ Ctx prep(int m) const {
        int b = m / 3136, r = m - b * 3136;
        int ty = r / 56, tx = r - ty * 56;
        int r0 = ty - 1 + py, r1 = r0 + 1;
        int c0 = tx - 1 + px, c1 = c0 + 1;
        bool r0v = (unsigned)r0 < 56u, r1v = (unsigned)r1 < 56u;
        bool c0v = (unsigned)c0 < 56u, c1v = (unsigned)c1 < 56u;
        Ctx c;
        c.base = in + (size_t)b * 192 * 3136;
        c.o0 = (r0v && c0v) ? r0 * 56 + c0 : -1;
        c.o1 = (r0v && c1v) ? r0 * 56 + c1 : -1;
        c.o2 = (r1v && c0v) ? r1 * 56 + c0 : -1;
        c.o3 = (r1v && c1v) ? r1 * 56 + c1 : -1;
        return c;
    }
    __device__ float4 load(const Ctx& c, int k) const {
        const float* p = c.base + (size_t)(k >> 2) * 3136;
        float4 v;
        v.x = (c.o0 >= 0) ? p[c.o0] : 0.f;
        v.y = (c.o1 >= 0) ? p[c.o1] : 0.f;
        v.z = (c.o2 >= 0) ? p[c.o2] : 0.f;
        v.w = (c.o3 >= 0) ? p[c.o3] : 0.f;
        return v;
    }
};

// ---------------- epilogues --------------------------------------------------
struct StConv {
    float* out; const float* scale; const float* shift; int py, px;
    __device__ void store(int m, int n, float v) const {
        v = fmaxf(v * scale[n] + shift[n], 0.f);
        int b = m / 3136, r = m - b * 3136;
        int ty = r / 56, tx = r - ty * 56;
        int y = 2 * ty + py, x = 2 * tx + px;
        out[((size_t)b * LTOK + y * H2 + x) * C2 + n] = v;
    }
};
struct StQKV {
    float* out; const float* bias;
    __device__ void store(int m, int n, float v) const {
        v += bias[n];
        int s3 = n / 96, rem = n - s3 * 96;
        int h = rem >> 4, d = rem & 15;
        if (s3 == 0) v *= 0.25f;
        int bw = m / 49, nn = m - bw * 49;
        out[(((size_t)(bw * 3 + s3) * 6 + h) * 49 + nn) * 16 + d] = v;
    }
};
struct StProj {
    float* out; const float* bias; int shift;
    __device__ void store(int m, int n, float v) const {
        int bw = m / 49, nn = m - bw * 49;
        int b = bw >> 8, wy = (bw >> 4) & 15, wx = bw & 15;
        int iy = nn / 7, ix = nn - iy * 7;
        int y = wy * 7 + iy + shift; if (y >= H2) y -= H2;
        int x = wx * 7 + ix + shift; if (x >= H2) x -= H2;
        out[((size_t)b * LTOK + y * H2 + x) * C2 + n] += v + bias[n];
    }
};
struct StGelu {
    __nv_bfloat16* outh; __nv_bfloat16* outl; const float* bias;
    __device__ void store(int m, int n, float v) const {
        v += bias[n];
        v = 0.5f * v * (1.0f + erff(v * 0.70710678118654752f));
        __nv_bfloat16 h, l;
        split1(v, h, l);
        size_t o = (size_t)m * HID + n;
        outh[o] = h; outl[o] = l;
    }
};
struct StFC2 {
    float* out; const float* bias;
    __device__ void store(int m, int n, float v) const {
        out[(size_t)m * C2 + n] += v + bias[n];
    }
};
struct StOut {
    float* out; const float* bias;
    __device__ void store(int m, int n, float v) const {
        v = fmaxf(v + bias[n], 0.f);
        int b = m / LTOK, pix = m - b * LTOK;
        out[((size_t)b * 48 + n) * LTOK + pix] = v;
    }
};

// ---------------- shared MMA/epilogue fragments ------------------------------
#define MMA_DECL \
    const int tid = threadIdx.x; \
    const int wid = tid >> 5, lane = tid & 31; \
    const int wm = wid & 3, wn = wid >> 2; \
    const int m0 = blockIdx.x << 7; \
    const int n0 = blockIdx.y * 96; \
    float acc[2][6][4]; \
    _Pragma("unroll") for (int mi = 0; mi < 2; mi++) \
    _Pragma("unroll") for (int ni = 0; ni < 6; ni++) \
    _Pragma("unroll") for (int r = 0; r < 4; r++) acc[mi][ni][r] = 0.f; \
    const uint32_t uAh = smem_u32(sAh), uAl = smem_u32(sAl); \
    const uint32_t uBh = smem_u32(sBh), uBl = smem_u32(sBl); \
    const uint32_t aoff = (uint32_t)((wm * 32 + (lane & 15)) * SROW + (lane >> 4) * 8); \
    const uint32_t boff = (uint32_t)((wn * 48 + (lane & 7)) * SROW + ((lane >> 3) & 1) * 8);

#define MMA_STAGE \
    _Pragma("unroll") \
    for (int ks = 0; ks < 48; ks += 16) { \
        uint32_t fAh[2][4], fAl[2][4]; \
        ldm_x4(fAh[0], uAh + (aoff + ks) * 2); \
        ldm_x4(fAh[1], uAh + (aoff + 16 * SROW + ks) * 2); \
        ldm_x4(fAl[0], uAl + (aoff + ks) * 2); \
        ldm_x4(fAl[1], uAl + (aoff + 16 * SROW + ks) * 2); \
        _Pragma("unroll") \
        for (int ni = 0; ni < 6; ni++) { \
            uint32_t bh[2], bl[2]; \
            ldm_x2(bh, uBh + (boff + ni * 8 * SROW + ks) * 2); \
            mma_bf16(acc[0][ni], fAh[0], bh); \
            mma_bf16(acc[1][ni], fAh[1], bh); \
            mma_bf16(acc[0][ni], fAl[0], bh); \
            mma_bf16(acc[1][ni], fAl[1], bh); \
            ldm_x2(bl, uBl + (boff + ni * 8 * SROW + ks) * 2); \
            mma_bf16(acc[0][ni], fAh[0], bl); \
            mma_bf16(acc[1][ni], fAh[1], bl); \
        } \
    }

#define MMA_EPI \
    _Pragma("unroll") for (int mi = 0; mi < 2; mi++) \
    _Pragma("unroll") for (int ni = 0; ni < 6; ni++) \
    _Pragma("unroll") for (int r = 0; r < 4; r++) { \
        int m = m0 + wm * 32 + mi * 16 + (lane >> 2) + ((r >> 1) << 3); \
        int n = n0 + wn * 48 + ni * 8 + ((lane & 3) << 1) + (r & 1); \
        if (n < Nt) st.store(m, n, acc[mi][ni][r]); \
    }

#define B_FILL \
    if (bact) { \
        uint16_t* dBh = sBh + brow * SROW + bhalf * 24; \
        uint16_t* dBl = sBl + brow * SROW + bhalf * 24; \
        _Pragma("unroll") \
        for (int j = 0; j < 3; j++) { \
            uint4 vh = make_uint4(0,0,0,0), vl = vh; \
            if (gBh) { \
                vh = *(const uint4*)(gBh + kb + j * 8); \
                vl = *(const uint4*)(gBl + kb + j * 8); \
            } \
            *(uint4*)(dBh + j * 8) = vh; \
            *(uint4*)(dBl + j * 8) = vl; \
        } \
    }

// bf16-plane A GEMM
template<class ST>
__global__ void __launch_bounds__(256, 2) mma_gemm_b(
        const __nv_bfloat16* __restrict__ Ahp, const __nv_bfloat16* __restrict__ Alp,
        ST st, const __nv_bfloat16* __restrict__ Bh, const __nv_bfloat16* __restrict__ Bl,
        int Nt, int K) {
    extern __shared__ uint16_t smx[];
    uint16_t* sAh = smx;
    uint16_t* sAl = smx + A_H;
    uint16_t* sBh = smx + 2 * A_H;
    uint16_t* sBl = sBh + B_H;
    MMA_DECL

    const int arow = tid & 127, ahalf = tid >> 7;
    const uint16_t* gAh = (const uint16_t*)Ahp + (size_t)(m0 + arow) * K + ahalf * 24;
    const uint16_t* gAl = (const uint16_t*)Alp + (size_t)(m0 + arow) * K + ahalf * 24;
    const bool bact = tid < 192;
    const int brow = bact ? (tid < 96 ? tid : tid - 96) : 0;
    const int bhalf = (tid >= 96 && bact) ? 1 : 0;
    const uint16_t* gBh = (bact && (n0 + brow) < Nt) ? (const uint16_t*)Bh + (size_t)(n0 + brow) * K + bhalf * 24 : (const uint16_t*)0;
    const uint16_t* gBl = gBh ? (const uint16_t*)Bl + (size_t)(n0 + brow) * K + bhalf * 24 : (const uint16_t*)0;

    const int nst = K / 48;
    for (int kc = 0; kc < nst; kc++) {
        const int kb = kc * 48;
        if (kc > 0) __syncthreads();
        {
            uint16_t* dAh = sAh + arow * SROW + ahalf * 24;
            uint16_t* dAl = sAl + arow * SROW + ahalf * 24;
            #pragma unroll
            for (int j = 0; j < 3; j++) {
                *(uint4*)(dAh + j * 8) = *(const uint4*)(gAh + kb + j * 8);
                *(uint4*)(dAl + j * 8) = *(const uint4*)(gAl + kb + j * 8);
            }
        }
        B_FILL
        __syncthreads();
        MMA_STAGE
    }
    MMA_EPI
}

// float-A GEMM (conv gather / out)
template<class AL, class ST>
__global__ void __launch_bounds__(256, 2) mma_gemm_f(
        AL al, ST st, const __nv_bfloat16* __restrict__ Bh, const __nv_bfloat16* __restrict__ Bl,
        int Nt, int K) {
    extern __shared__ uint16_t smx[];
    uint16_t* sAh = smx;
    uint16_t* sAl = smx + A_H;
    uint16_t* sBh = smx + 2 * A_H;
    uint16_t* sBl = sBh + B_H;
    MMA_DECL

    const int arow = tid & 127, ahalf = tid >> 7;
    typename AL::Ctx ctx = al.prep(m0 + arow);
    const bool bact = tid < 192;
    const int brow = bact ? (tid < 96 ? tid : tid - 96) : 0;
    const int bhalf = (tid >= 96 && bact) ? 1 : 0;
    const uint16_t* gBh = (bact && (n0 + brow) < Nt) ? (const uint16_t*)Bh + (size_t)(n0 + brow) * K + bhalf * 24 : (const uint16_t*)0;
    const uint16_t* gBl = gBh ? (const uint16_t*)Bl + (size_t)(n0 + brow) * K + bhalf * 24 : (const uint16_t*)0;

    const int nst = K / 48;
    for (int kc = 0; kc < nst; kc++) {
        const int kb = kc * 48;
        if (kc > 0) __syncthreads();
        {
            uint16_t* dAh = sAh + arow * SROW + ahalf * 24;
            uint16_t* dAl = sAl + arow * SROW + ahalf * 24;
            #pragma unroll
            for (int j = 0; j < 6; j++) {
                float4 v = al.load(ctx, kb + ahalf * 24 + j * 4);
                uint2 h, l;
                split4(v, h, l);
                *(uint2*)(dAh + j * 4) = h;
                *(uint2*)(dAl + j * 4) = l;
            }
        }
        B_FILL
        __syncthreads();
        MMA_STAGE
    }
    MMA_EPI
}

// ---------------- LayerNorm (writes bf16 hi/lo planes) -----------------------
__device__ __forceinline__ float warp_sum(float v) {
    #pragma unroll
    for (int o = 16; o; o >>= 1) v += __shfl_xor_sync(0xffffffffu, v, o);
    return v;
}
__device__ __forceinline__ void ln_store3(__nv_bfloat16* dh, __nv_bfloat16* dl, int lane,
                                          float v0, float v1, float v2) {
    __nv_bfloat16 h, l;
    split1(v0, h, l); dh[lane] = h;      dl[lane] = l;
    split1(v1, h, l); dh[lane + 32] = h; dl[lane + 32] = l;
    split1(v2, h, l); dh[lane + 64] = h; dl[lane + 64] = l;
}
__global__ void __launch_bounds__(128) ln_part_kernel(const float* __restrict__ src,
                                                      __nv_bfloat16* __restrict__ dh,
                                                      __nv_bfloat16* __restrict__ dl,
                                                      const float* __restrict__ gg,
                                                      const float* __restrict__ be,
                                                      int shift) {
    int warp = threadIdx.x >> 5, lane = threadIdx.x & 31;
    int gidx = blockIdx.x * 4 + warp;
    int bw = gidx / 49, nn = gidx - bw * 49;
    int b = bw >> 8, wy = (bw >> 4) & 15, wx = bw & 15;
    int iy = nn / 7, ix = nn - iy * 7;
    int ys = wy * 7 + iy + shift; if (ys >= H2) ys -= H2;
    int xs = wx * 7 + ix + shift; if (xs >= H2) xs -= H2;
    const float* sp = src + ((size_t)b * LTOK + ys * H2 + xs) * C2;
    float v0 = sp[lane], v1 = sp[lane + 32], v2 = sp[lane + 64];
    float mean = warp_sum(v0 + v1 + v2) * (1.f / 96.f);
    float d0 = v0 - mean, d1 = v1 - mean, d2 = v2 - mean;
    float var = warp_sum(d0*d0 + d1*d1 + d2*d2) * (1.f / 96.f);
    float inv = rsqrtf(var + 1e-5f);
    ln_store3(dh + (size_t)gidx * C2, dl + (size_t)gidx * C2, lane,
              d0 * inv * gg[lane] + be[lane],
              d1 * inv * gg[lane + 32] + be[lane + 32],
              d2 * inv * gg[lane + 64] + be[lane + 64]);
}
__global__ void __launch_bounds__(128) ln_plain_kernel(const float* __restrict__ src,
                                                       __nv_bfloat16* __restrict__ dh,
                                                       __nv_bfloat16* __restrict__ dl,
                                                       const float* __restrict__ gg,
                                                       const float* __restrict__ be) {
    int warp = threadIdx.x >> 5, lane = threadIdx.x & 31;
    size_t gidx = (size_t)blockIdx.x * 4 + warp;
    const float* sp = src + gidx * C2;
    float v0 = sp[lane], v1 = sp[lane + 32], v2 = sp[lane + 64];
    float mean = warp_sum(v0 + v1 + v2) * (1.f / 96.f);
    float d0 = v0 - mean, d1 = v1 - mean, d2 = v2 - mean;
    float var = warp_sum(d0*d0 + d1*d1 + d2*d2) * (1.f / 96.f);
    float inv = rsqrtf(var + 1e-5f);
    ln_store3(dh + gidx * C2, dl + gidx * C2, lane,
              d0 * inv * gg[lane] + be[lane],
              d1 * inv * gg[lane + 32] + be[lane + 32],
              d2 * inv * gg[lane + 64] + be[lane + 64]);
}

// ---------------- window attention (writes bf16 hi/lo planes) ----------------
__global__ void __launch_bounds__(128) attn_kernel(const float* __restrict__ qkv,
                                                   const float* __restrict__ rel,
                                                   __nv_bfloat16* __restrict__ outh,
                                                   __nv_bfloat16* __restrict__ outl,
                                                   int shifted) {
    __shared__ float sq[2*784], sk[2*784], sv[2*784], srel[2*169];
    __shared__ int slbl[49];
    const int bw = blockIdx.x, h0 = blockIdx.y * 2;
    const int tid = threadIdx.x;

    for (int i = tid; i < 2 * 784; i += 128) {
        int hh = i / 784, idx = i - hh * 784;
        int h = h0 + hh;
        sq[i] = qkv[(((size_t)(bw * 3 + 0) * 6 + h)) * 784 + idx];
        sk[i] = qkv[(((size_t)(bw * 3 + 1) * 6 + h)) * 784 + idx];
        sv[i] = qkv[(((size_t)(bw * 3 + 2) * 6 + h)) * 784 + idx];
    }
    for (int i = tid; i < 2 * 169; i += 128) {
        int hh = i / 169, idx = i - hh * 169;
        srel[i] = rel[idx * 6 + h0 + hh];
    }
    if (tid < 49) {
        if (shifted) {
            int wy = (bw >> 4) & 15, wx = bw & 15;
            int yy = wy * 7 + tid / 7, xx = wx * 7 + tid % 7;
            int ry = (yy < 105) ? 0 : ((yy < 109) ? 1 : 2);
            int rx = (xx < 105) ? 0 : ((xx < 109) ? 1 : 2);
            slbl[tid] = ry * 3 + rx;
        } else slbl[tid] = 0;
    }
    __syncthreads();

    const int h2 = tid >> 6, n = tid & 63;
    if (n < 49) {
        const float* qh = sq + h2 * 784;
        const float* kh = sk + h2 * 784;
        const float* vh = sv + h2 * 784;
        const float* rh = srel + h2 * 169;
        const int iy = n / 7, ix = n - iy * 7;
        float4 q0 = *(const float4*)&qh[n*16+0];
        float4 q1 = *(const float4*)&qh[n*16+4];
        float4 q2 = *(const float4*)&qh[n*16+8];
        float4 q3 = *(const float4*)&qh[n*16+12];
        const int mylbl = slbl[n];
        float s[49];
        float mx = -1e30f;
        #pragma unroll
        for (int m = 0; m < 49; m++) {
            int jy = m / 7, jx = m - jy * 7;
            float4 k0 = *(const float4*)&kh[m*16+0];
            float4 k1 = *(const float4*)&kh[m*16+4];
            float4 k2 = *(const float4*)&kh[m*16+8];
            float4 k3 = *(const float4*)&kh[m*16+12];
            float d = q0.x*k0.x+q0.y*k0.y+q0.z*k0.z+q0.w*k0.w
                    + q1.x*k1.x+q1.y*k1.y+q1.z*k1.z+q1.w*k1.w
                    + q2.x*k2.x+q2.y*k2.y+q2.z*k2.z+q2.w*k2.w
                    + q3.x*k3.x+q3.y*k3.y+q3.z*k3.z+q3.w*k3.w;
            d += rh[(iy - jy + 6) * 13 + (ix - jx + 6)];
            if (shifted && slbl[m] != mylbl) d -= 100.f;
            s[m] = d;
            mx = fmaxf(mx, d);
        }
        float sum = 0.f;
        #pragma unroll
        for (int m = 0; m < 49; m++) {
            float e = __expf(s[m] - mx);
            s[m] = e;
            sum += e;
        }
        float inv = 1.f / sum;
        float o[16];
        #pragma unroll
        for (int d = 0; d < 16; d++) o[d] = 0.f;
        #pragma unroll
        for (int m = 0; m < 49; m++) {
            float p = s[m] * inv;
            float4 v0 = *(const float4*)&vh[m*16+0];
            float4 v1 = *(const float4*)&vh[m*16+4];
            float4 v2 = *(const float4*)&vh[m*16+8];
            float4 v3 = *(const float4*)&vh[m*16+12];
            o[0]+=p*v0.x; o[1]+=p*v0.y; o[2]+=p*v0.z; o[3]+=p*v0.w;
            o[4]+=p*v1.x; o[5]+=p*v1.y; o[6]+=p*v1.z; o[7]+=p*v1.w;
            o[8]+=p*v2.x; o[9]+=p*v2.y; o[10]+=p*v2.z; o[11]+=p*v2.w;
            o[12]+=p*v3.x; o[13]+=p*v3.y; o[14]+=p*v3.z; o[15]+=p*v3.w;
        }
        uint32_t uh[8], ul[8];
        #pragma unroll
        for (int d = 0; d < 8; d++) split2(o[2*d], o[2*d+1], uh[d], ul[d]);
        size_t o0 = ((size_t)bw * 49 + n) * C2 + (h0 + h2) * 16;
        ((uint4*)(outh + o0))[0] = make_uint4(uh[0], uh[1], uh[2], uh[3]);
        ((uint4*)(outh + o0))[1] = make_uint4(uh[4], uh[5], uh[6], uh[7]);
        ((uint4*)(outl + o0))[0] = make_uint4(ul[0], ul[1], ul[2], ul[3]);
        ((uint4*)(outl + o0))[1] = make_uint4(ul[4], ul[5], ul[6], ul[7]);
    }
}

// ---------------- launch -----------------------------------------------------
extern "C" void kernel_launch(void* const* d_in, const int* in_sizes, int n_in,
                              void* d_out, int out_size) {
    (void)in_sizes; (void)n_in; (void)out_size;
    const float* x     = (const float*)d_in[0];
    const float* up_w  = (const float*)d_in[1];
    const float* up_b  = (const float*)d_in[2];
    const float* bn_g  = (const float*)d_in[3];
    const float* bn_b  = (const float*)d_in[4];
    const float* bn_m  = (const float*)d_in[5];
    const float* bn_v  = (const float*)d_in[6];
    const float* n1g   = (const float*)d_in[7];
    const float* n1b   = (const float*)d_in[8];
    const float* qkvw  = (const float*)d_in[9];
    const float* qkvb  = (const float*)d_in[10];
    const float* projw = (const float*)d_in[11];
    const float* projb = (const float*)d_in[12];
    const float* rel   = (const float*)d_in[13];
    const float* n2g   = (const float*)d_in[14];
    const float* n2b   = (const float*)d_in[15];
    const float* f1w   = (const float*)d_in[16];
    const float* f1b   = (const float*)d_in[17];
    const float* f2w   = (const float*)d_in[18];
    const float* f2b   = (const float*)d_in[19];
    const float* outw  = (const float*)d_in[20];
    const float* outb  = (const float*)d_in[21];
    float* out = (float*)d_out;

    float *bX, *bQ, *scl, *sft;
    __nv_bfloat16 *bWh, *bWl, *bAh, *bAl, *bHh, *bHl, *wh, *wl;
    cudaGetSymbolAddress((void**)&bX,  d_bufX);
    cudaGetSymbolAddress((void**)&bQ,  d_bufQ);
    cudaGetSymbolAddress((void**)&bWh, d_bWh);
    cudaGetSymbolAddress((void**)&bWl, d_bWl);
    cudaGetSymbolAddress((void**)&bAh, d_bAh);
    cudaGetSymbolAddress((void**)&bAl, d_bAl);
    cudaGetSymbolAddress((void**)&bHh, d_bHh);
    cudaGetSymbolAddress((void**)&bHl, d_bHl);
    cudaGetSymbolAddress((void**)&wh,  d_wh);
    cudaGetSymbolAddress((void**)&wl,  d_wl);
    cudaGetSymbolAddress((void**)&scl, d_cscale);
    cudaGetSymbolAddress((void**)&sft, d_cshift);

    cudaFuncSetAttribute(mma_gemm_f<ALConv,   StConv>, cudaFuncAttributeMaxDynamicSharedMemorySize, SMEM_BYTES);
    cudaFuncSetAttribute(mma_gemm_f<ALDirect, StOut>,  cudaFuncAttributeMaxDynamicSharedMemorySize, SMEM_BYTES);
    cudaFuncSetAttribute(mma_gemm_b<StQKV>,  cudaFuncAttributeMaxDynamicSharedMemorySize, SMEM_BYTES);
    cudaFuncSetAttribute(mma_gemm_b<StProj>, cudaFuncAttributeMaxDynamicSharedMemorySize, SMEM_BYTES);
    cudaFuncSetAttribute(mma_gemm_b<StGelu>, cudaFuncAttributeMaxDynamicSharedMemorySize, SMEM_BYTES);
    cudaFuncSetAttribute(mma_gemm_b<StFC2>,  cudaFuncAttributeMaxDynamicSharedMemorySize, SMEM_BYTES);

    prep_conv<<<64, 256>>>(up_w, up_b, bn_g, bn_b, bn_m, bn_v);
    prep_w<<<221, 512>>>(qkvw, projw, f1w, f2w, outw);

    for (int p = 0; p < 4; p++) {
        ALConv al; al.in = x; al.py = p >> 1; al.px = p & 1;
        StConv st; st.out = bX; st.scale = scl; st.shift = sft; st.py = p >> 1; st.px = p & 1;
        mma_gemm_f<<<dim3(196, 1), 256, SMEM_BYTES>>>(al, st, wh + OFF_WC + (size_t)p * 96 * 768,
                                                      wl + OFF_WC + (size_t)p * 96 * 768, 96, 768);
    }

    for (int i = 0; i < 2; i++) {
        int sh = i ? 3 : 0;
        ln_part_kernel<<<25088, 128>>>(bX, bWh, bWl, n1g + i * 96, n1b + i * 96, sh);

        { StQKV st; st.out = bQ; st.bias = qkvb + i * 288;
          mma_gemm_b<<<dim3(784, 3), 256, SMEM_BYTES>>>(bWh, bWl, st,
              wh + OFF_QKV + (size_t)i * 27648, wl + OFF_QKV + (size_t)i * 27648, 288, 96); }

        attn_kernel<<<dim3(2048, 3), 128>>>(bQ, rel + (size_t)i * 169 * 6, bAh, bAl, sh);

        { StProj st; st.out = bX; st.bias = projb + i * 96; st.shift = sh;
          mma_gemm_b<<<dim3(784, 1), 256, SMEM_BYTES>>>(bAh, bAl, st,
              wh + OFF_PROJ + (size_t)i * 9216, wl + OFF_PROJ + (size_t)i * 9216, 96, 96); }

        ln_plain_kernel<<<25088, 128>>>(bX, bWh, bWl, n2g + i * 96, n2b + i * 96);

        { StGelu st; st.outh = bHh; st.outl = bHl; st.bias = f1b + i * HID;
          mma_gemm_b<<<dim3(784, 4), 256, SMEM_BYTES>>>(bWh, bWl, st,
              wh + OFF_F1 + (size_t)i * 36864, wl + OFF_F1 + (size_t)i * 36864, HID, 96); }

        { StFC2 st; st.out = bX; st.bias = f2b + i * 96;
          mma_gemm_b<<<dim3(784, 1), 256, SMEM_BYTES>>>(bHh, bHl, st,
              wh + OFF_F2 + (size_t)i * 36864, wl + OFF_F2 + (size_t)i * 36864, 96, 384); }
    }

    { ALDirect al; al.A = bX; al.K = 96;
      StOut st; st.out = out; st.bias = outb;
      mma_gemm_f<<<dim3(784, 1), 256, SMEM_BYTES>>>(al, st, wh + OFF_OUT, wl + OFF_OUT, 48, 96); }
}

// round 11
// speedup vs baseline: 1.3370x; 1.3370x over previous
#include <cuda_runtime.h>
#include <cuda_bf16.h>
#include <math.h>
#include <stdint.h>

#define CB 8
#define C2 96
#define H2 112
#define LTOK 12544
#define NWB 2048
#define HID 384

#define SROW 56                // smem row pitch (halves), 112B, conflict-free ldmatrix
#define PS_A 7168              // halves per A plane per stage (128*56)
#define PS_B 5376              // halves per B plane per stage (96*56)
#define PS_STG 25088           // halves per stage: 2*(PS_A+PS_B)
#define SMEM_BYTES (2*PS_STG*2)  // two stages, bytes (100352)

// weight arena offsets (elements)
#define OFF_WC   0
#define OFF_QKV  294912
#define OFF_PROJ 350208
#define OFF_F1   368640
#define OFF_F2   442368
#define OFF_OUT  516096
#define TOTW     520704

__device__ float d_bufX[CB*LTOK*C2];
__device__ float d_bufQ[NWB*3*6*49*16];
__device__ __nv_bfloat16 d_bWh[CB*LTOK*C2], d_bWl[CB*LTOK*C2];
__device__ __nv_bfloat16 d_bAh[CB*LTOK*C2], d_bAl[CB*LTOK*C2];
__device__ __nv_bfloat16 d_bHh[CB*LTOK*HID], d_bHl[CB*LTOK*HID];
__device__ __nv_bfloat16 d_wh[TOTW], d_wl[TOTW];
__device__ float d_cscale[96];
__device__ float d_cshift[96];

// ---------------- helpers ----------------
__device__ __forceinline__ uint32_t smem_u32(const void* p) {
    uint32_t a;
    asm("{ .reg .u64 t; cvta.to.shared.u64 t, %1; cvt.u32.u64 %0, t; }" : "=r"(a) : "l"(p));
    return a;
}
__device__ __forceinline__ void ldm_x4(uint32_t* r, uint32_t addr) {
    asm volatile("ldmatrix.sync.aligned.m8n8.x4.shared.b16 {%0,%1,%2,%3}, [%4];"
        : "=r"(r[0]), "=r"(r[1]), "=r"(r[2]), "=r"(r[3]) : "r"(addr));
}
__device__ __forceinline__ void ldm_x2(uint32_t* r, uint32_t addr) {
    asm volatile("ldmatrix.sync.aligned.m8n8.x2.shared.b16 {%0,%1}, [%2];"
        : "=r"(r[0]), "=r"(r[1]) : "r"(addr));
}
__device__ __forceinline__ void mma_bf16(float* c, const uint32_t* a, const uint32_t* b) {
    asm volatile("mma.sync.aligned.m16n8k16.row.col.f32.bf16.bf16.f32 "
        "{%0,%1,%2,%3}, {%4,%5,%6,%7}, {%8,%9}, {%0,%1,%2,%3};"
        : "+f"(c[0]), "+f"(c[1]), "+f"(c[2]), "+f"(c[3])
        : "r"(a[0]), "r"(a[1]), "r"(a[2]), "r"(a[3]), "r"(b[0]), "r"(b[1]));
}
__device__ __forceinline__ void cpa16(uint32_t d, const void* g) {
    asm volatile("cp.async.ca.shared.global [%0], [%1], 16;" :: "r"(d), "l"(g) : "memory");
}
#define CP_COMMIT() asm volatile("cp.async.commit_group;" ::: "memory")
#define CP_WAIT1()  asm volatile("cp.async.wait_group 1;" ::: "memory")
#define CP_WAIT0()  asm volatile("cp.async.wait_group 0;" ::: "memory")

__device__ __forceinline__ void split1(float x, __nv_bfloat16& h, __nv_bfloat16& l) {
    h = __float2bfloat16_rn(x);
    l = __float2bfloat16_rn(x - __bfloat162float(h));
}
__device__ __forceinline__ void split2(float x, float y, uint32_t& h, uint32_t& l) {
    __nv_bfloat16 hx, lx, hy, ly;
    split1(x, hx, lx); split1(y, hy, ly);
    h = ((uint32_t)__bfloat16_as_ushort(hy) << 16) | (uint32_t)__bfloat16_as_ushort(hx);
    l = ((uint32_t)__bfloat16_as_ushort(ly) << 16) | (uint32_t)__bfloat16_as_ushort(lx);
}
__device__ __forceinline__ void split4(float4 a, uint2& h, uint2& l) {
    split2(a.x, a.y, h.x, l.x);
    split2(a.z, a.w, h.y, l.y);
}

// ---------------- prep ----------------
__global__ void prep_conv(const float* __restrict__ up_w, const float* __restrict__ up_b,
                          const float* __restrict__ bn_g, const float* __restrict__ bn_b,
                          const float* __restrict__ bn_m, const float* __restrict__ bn_v) {
    int tid = blockIdx.x * blockDim.x + threadIdx.x;
    if (tid < 96) {
        float s = bn_g[tid] * rsqrtf(bn_v[tid] + 1e-5f);
        d_cscale[tid] = s;
        d_cshift[tid] = (up_b[tid] - bn_m[tid]) * s + bn_b[tid];
    }
    int total = 4 * 96 * 192;
    for (int idx = tid; idx < total; idx += gridDim.x * blockDim.x) {
        int p  = idx / (96 * 192);
        int r  = idx % (96 * 192);
        int co = r / 192, ci = r % 192;
        int py = p >> 1, px = p & 1;
        const float* w = up_w + ((size_t)co * 192 + ci) * 9;
        float cs[3][2];
        #pragma unroll
        for (int ky = 0; ky < 3; ky++) {
            float w0 = w[ky*3], w1 = w[ky*3+1], w2 = w[ky*3+2];
            cs[ky][0] = (px == 0) ? w0 : (w0 + w1);
            cs[ky][1] = (px == 0) ? (w1 + w2) : w2;
        }
        size_t dst = (size_t)OFF_WC + ((size_t)p * 96 + co) * 768 + ci * 4;
        float v[4];
        #pragma unroll
        for (int b2 = 0; b2 < 2; b2++) {
            v[b2]     = (py == 0) ? cs[0][b2] : (cs[0][b2] + cs[1][b2]);
            v[2 + b2] = (py == 0) ? (cs[1][b2] + cs[2][b2]) : cs[2][b2];
        }
        #pragma unroll
        for (int j = 0; j < 4; j++) {
            __nv_bfloat16 h, l;
            split1(v[j], h, l);
            d_wh[dst + j] = h; d_wl[dst + j] = l;
        }
    }
}

__global__ void prep_w(const float* __restrict__ qkvw, const float* __restrict__ projw,
                       const float* __restrict__ f1w,  const float* __restrict__ f2w,
                       const float* __restrict__ outw) {
    int tid = blockIdx.x * blockDim.x + threadIdx.x;
    int total = TOTW - OFF_QKV;
    for (int idx = tid; idx < total; idx += gridDim.x * blockDim.x) {
        float v; size_t dst = OFF_QKV + idx;
        int r = idx;
        if (r < 55296)                 v = qkvw[r];
        else if ((r -= 55296) < 18432) v = projw[r];
        else if ((r -= 18432) < 73728) v = f1w[r];
        else if ((r -= 73728) < 73728) v = f2w[r];
        else                           v = outw[r - 73728];
        __nv_bfloat16 h, l;
        split1(v, h, l);
        d_wh[dst] = h; d_wl[dst] = l;
    }
}

// ---------------- float-A loaders (parity from blockIdx.z for conv) ----------
struct ALDirect {
    const float* A; int K;
    struct Ctx { const float* p; };
    __device__ Ctx prep(int m) const { Ctx c; c.p = A + (size_t)m * K; return c; }
    __device__ float4 load(const Ctx& c, int k) const { return *(const float4*)(c.p + k); }
};
struct ALConv {
    const float* in;
    struct Ctx { const float* base; int o0, o1, o2, o3; };
    __device__ Ctx prep(int m) const {
        int py = blockIdx.z >> 1, px = blockIdx.z & 1;
        int b = m / 3136, r = m - b * 3136;
        int ty = r / 56, tx = r - ty * 56;
        int r0 = ty - 1 + py, r1 = r0 + 1;
        int c0 = tx - 1 + px, c1 = c0 + 1;
        bool r0v = (unsigned)r0 < 56u, r1v = (unsigned)r1 < 56u;
        bool c0v = (unsigned)c0 < 56u, c1v = (unsigned)c1 < 56u;
        Ctx c;
        c.base = in + (size_t)b * 192 * 3136;
        c.o0 = (r0v && c0v) ? r0 * 56 + c0 : -1;
        c.o1 = (r0v && c1v) ? r0 * 56 + c1 : -1;
        c.o2 = (r1v && c0v) ? r1 * 56 + c0 : -1;
        c.o3 = (r1v && c1v) ? r1 * 56 + c1 : -1;
        return c;
    }
    __device__ float4 load(const Ctx& c, int k) const {
        const float* p = c.base + (size_t)(k >> 2) * 3136;
        float4 v;
        v.x = (c.o0 >= 0) ? p[c.o0] : 0.f;
        v.y = (c.o1 >= 0) ? p[c.o1] : 0.f;
        v.z = (c.o2 >= 0) ? p[c.o2] : 0.f;
        v.w = (c.o3 >= 0) ? p[c.o3] : 0.f;
        return v;
    }
};

// ---------------- epilogues --------------------------------------------------
struct StConv {
    float* out; const float* scale; const float* shift;
    __device__ void store(int m, int n, float v) const {
        int py = blockIdx.z >> 1, px = blockIdx.z & 1;
        v = fmaxf(v * scale[n] + shift[n], 0.f);
        int b = m / 3136, r = m - b * 3136;
        int ty = r / 56, tx = r - ty * 56;
        int y = 2 * ty + py, x = 2 * tx + px;
        out[((size_t)b * LTOK + y * H2 + x) * C2 + n] = v;
    }
};
struct StQKV {
    float* out; const float* bias;
    __device__ void store(int m, int n, float v) const {
        v += bias[n];
        int s3 = n / 96, rem = n - s3 * 96;
        int h = rem >> 4, d = rem & 15;
        if (s3 == 0) v *= 0.25f;
        int bw = m / 49, nn = m - bw * 49;
        out[(((size_t)(bw * 3 + s3) * 6 + h) * 49 + nn) * 16 + d] = v;
    }
};
struct StProj {
    float* out; const float* bias; int shift;
    __device__ void store(int m, int n, float v) const {
        int bw = m / 49, nn = m - bw * 49;
        int b = bw >> 8, wy = (bw >> 4) & 15, wx = bw & 15;
        int iy = nn / 7, ix = nn - iy * 7;
        int y = wy * 7 + iy + shift; if (y >= H2) y -= H2;
        int x = wx * 7 + ix + shift; if (x >= H2) x -= H2;
        out[((size_t)b * LTOK + y * H2 + x) * C2 + n] += v + bias[n];
    }
};
struct StGelu {
    __nv_bfloat16* outh; __nv_bfloat16* outl; const float* bias;
    __device__ void store(int m, int n, float v) const {
        v += bias[n];
        v = 0.5f * v * (1.0f + erff(v * 0.70710678118654752f));
        __nv_bfloat16 h, l;
        split1(v, h, l);
        size_t o = (size_t)m * HID + n;
        outh[o] = h; outl[o] = l;
    }
};
struct StFC2 {
    float* out; const float* bias;
    __device__ void store(int m, int n, float v) const {
        out[(size_t)m * C2 + n] += v + bias[n];
    }
};
struct StOut {
    float* out; const float* bias;
    __device__ void store(int m, int n, float v) const {
        v = fmaxf(v + bias[n], 0.f);
        int b = m / LTOK, pix = m - b * LTOK;
        out[((size_t)b * 48 + n) * LTOK + pix] = v;
    }
};

// ---------------- MMA stage + epilogue ---------------------------------------
__device__ __forceinline__ void mma_stage(uint32_t stg, uint32_t aoff, uint32_t boff,
                                          float (&acc)[2][6][4]) {
    const uint32_t uAh = stg, uAl = stg + PS_A * 2;
    const uint32_t uBh = stg + 2 * PS_A * 2, uBl = stg + (2 * PS_A + PS_B) * 2;
    #pragma unroll
    for (int ks = 0; ks < 48; ks += 16) {
        uint32_t fAh[2][4], fAl[2][4];
        ldm_x4(fAh[0], uAh + (aoff + ks) * 2);
        ldm_x4(fAh[1], uAh + (aoff + 16 * SROW + ks) * 2);
        ldm_x4(fAl[0], uAl + (aoff + ks) * 2);
        ldm_x4(fAl[1], uAl + (aoff + 16 * SROW + ks) * 2);
        #pragma unroll
        for (int ni = 0; ni < 6; ni++) {
            uint32_t bh[2], bl[2];
            ldm_x2(bh, uBh + (boff + ni * 8 * SROW + ks) * 2);
            mma_bf16(acc[0][ni], fAh[0], bh);
            mma_bf16(acc[1][ni], fAh[1], bh);
            mma_bf16(acc[0][ni], fAl[0], bh);
            mma_bf16(acc[1][ni], fAl[1], bh);
            ldm_x2(bl, uBl + (boff + ni * 8 * SROW + ks) * 2);
            mma_bf16(acc[0][ni], fAh[0], bl);
            mma_bf16(acc[1][ni], fAh[1], bl);
        }
    }
}

#define MMA_DECL \
    const int tid = threadIdx.x; \
    const int wid = tid >> 5, lane = tid & 31; \
    const int wm = wid & 3, wn = wid >> 2; \
    const int m0 = blockIdx.x << 7; \
    const int n0 = blockIdx.y * 96; \
    float acc[2][6][4]; \
    _Pragma("unroll") for (int mi = 0; mi < 2; mi++) \
    _Pragma("unroll") for (int ni = 0; ni < 6; ni++) \
    _Pragma("unroll") for (int r = 0; r < 4; r++) acc[mi][ni][r] = 0.f; \
    const uint32_t sbase = smem_u32(smx); \
    const uint32_t aoff = (uint32_t)((wm * 32 + (lane & 15)) * SROW + (lane >> 4) * 8); \
    const uint32_t boff = (uint32_t)((wn * 48 + (lane & 7)) * SROW + ((lane >> 3) & 1) * 8);

#define MMA_EPI \
    _Pragma("unroll") for (int mi = 0; mi < 2; mi++) \
    _Pragma("unroll") for (int ni = 0; ni < 6; ni++) \
    _Pragma("unroll") for (int r = 0; r < 4; r++) { \
        int m = m0 + wm * 32 + mi * 16 + (lane >> 2) + ((r >> 1) << 3); \
        int n = n0 + wn * 48 + ni * 8 + ((lane & 3) << 1) + (r & 1); \
        if (n < Nt) st.store(m, n, acc[mi][ni][r]); \
    }

// ---------------- plane-A GEMM, cp.async ping-pong ---------------------------
template<class ST>
__global__ void __launch_bounds__(256) mma_gemm_p(
        const __nv_bfloat16* __restrict__ Ahp, const __nv_bfloat16* __restrict__ Alp,
        ST st, const __nv_bfloat16* __restrict__ Bh, const __nv_bfloat16* __restrict__ Bl,
        int Nt, int K) {
    extern __shared__ uint16_t smx[];
    MMA_DECL

    const int arow = tid & 127, apl = tid >> 7;
    const uint16_t* gA = (const uint16_t*)(apl ? Alp : Ahp) + (size_t)(m0 + arow) * K;
    const bool bact = tid < 192;
    const int brow = bact ? (tid < 96 ? tid : tid - 96) : 0;
    const int bpl = (tid >= 96) ? 1 : 0;
    const uint16_t* gB = (const uint16_t*)(bpl ? Bl : Bh) + (size_t)(n0 + brow) * K;
    const uint32_t dA = sbase + (uint32_t)((apl ? PS_A : 0) + arow * SROW) * 2;
    const uint32_t dB = sbase + (uint32_t)(2 * PS_A + (bpl ? PS_B : 0) + brow * SROW) * 2;

    const int nst = K / 48;
    #pragma unroll
    for (int j = 0; j < 6; j++) cpa16(dA + j * 16, gA + j * 8);
    if (bact) {
        #pragma unroll
        for (int j = 0; j < 6; j++) cpa16(dB + j * 16, gB + j * 8);
    }
    CP_COMMIT();
    for (int kc = 0; kc < nst; kc++) {
        if (kc + 1 < nst) {
            const uint32_t so = (uint32_t)((kc + 1) & 1) * (PS_STG * 2);
            #pragma unroll
            for (int j = 0; j < 6; j++) cpa16(dA + so + j * 16, gA + (kc + 1) * 48 + j * 8);
            if (bact) {
                #pragma unroll
                for (int j = 0; j < 6; j++) cpa16(dB + so + j * 16, gB + (kc + 1) * 48 + j * 8);
            }
            CP_COMMIT();
            CP_WAIT1();
        } else CP_WAIT0();
        __syncthreads();
        mma_stage(sbase + (uint32_t)(kc & 1) * (PS_STG * 2), aoff, boff, acc);
        __syncthreads();
    }
    MMA_EPI
}

// ---------------- float-A GEMM, reg-prefetch A + cp.async B ------------------
template<class AL, class ST>
__global__ void __launch_bounds__(256) mma_gemm_f(
        AL al, ST st, const __nv_bfloat16* __restrict__ Bh0, const __nv_bfloat16* __restrict__ Bl0,
        int Nt, int K, int wstride) {
    extern __shared__ uint16_t smx[];
    const __nv_bfloat16* Bh = Bh0 + (size_t)blockIdx.z * wstride;
    const __nv_bfloat16* Bl = Bl0 + (size_t)blockIdx.z * wstride;
    MMA_DECL

    const int arow = tid & 127, ahalf = tid >> 7;   // 24 k-elems each
    typename AL::Ctx ctx = al.prep(m0 + arow);
    const bool bact = tid < 192;
    const int brow = bact ? (tid < 96 ? tid : tid - 96) : 0;
    const int bpl = (tid >= 96) ? 1 : 0;
    int brc = brow; if (n0 + brc >= Nt) brc = Nt - 1 - n0;
    const uint16_t* gB = (const uint16_t*)(bpl ? Bl : Bh) + (size_t)(n0 + brc) * K;
    const uint32_t dB = sbase + (uint32_t)(2 * PS_A + (bpl ? PS_B : 0) + brow * SROW) * 2;
    const uint32_t dAbase = (uint32_t)(arow * SROW + ahalf * 24) * 2;

    const int nst = K / 48;
    float4 cur[6], nxt[6];
    #pragma unroll
    for (int j = 0; j < 6; j++) cur[j] = al.load(ctx, ahalf * 24 + j * 4);
    if (bact) {
        #pragma unroll
        for (int j = 0; j < 6; j++) cpa16(dB + j * 16, gB + j * 8);
    }
    CP_COMMIT();

    for (int kc = 0; kc < nst; kc++) {
        if (kc + 1 < nst) {
            #pragma unroll
            for (int j = 0; j < 6; j++) nxt[j] = al.load(ctx, (kc + 1) * 48 + ahalf * 24 + j * 4);
            const uint32_t so = (uint32_t)((kc + 1) & 1) * (PS_STG * 2);
            if (bact) {
                #pragma unroll
                for (int j = 0; j < 6; j++) cpa16(dB + so + j * 16, gB + (kc + 1) * 48 + j * 8);
            }
            CP_COMMIT();
        }
        {
            const uint32_t so = sbase + (uint32_t)(kc & 1) * (PS_STG * 2);
            uint32_t dAh = so + dAbase;
            uint32_t dAl = dAh + PS_A * 2;
            #pragma unroll
            for (int j = 0; j < 6; j++) {
                uint2 h, l;
                split4(cur[j], h, l);
                asm volatile("st.shared.v2.b32 [%0], {%1, %2};" :: "r"(dAh + j * 8), "r"(h.x), "r"(h.y));
                asm volatile("st.shared.v2.b32 [%0], {%1, %2};" :: "r"(dAl + j * 8), "r"(l.x), "r"(l.y));
            }
        }
        if (kc + 1 < nst) { CP_WAIT1(); } else { CP_WAIT0(); }
        __syncthreads();
        mma_stage(sbase + (uint32_t)(kc & 1) * (PS_STG * 2), aoff, boff, acc);
        __syncthreads();
        #pragma unroll
        for (int j = 0; j < 6; j++) cur[j] = nxt[j];
    }
    MMA_EPI
}

// ---------------- LayerNorm (writes bf16 planes) -----------------------------
__device__ __forceinline__ float warp_sum(float v) {
    #pragma unroll
    for (int o = 16; o; o >>= 1) v += __shfl_xor_sync(0xffffffffu, v, o);
    return v;
}
__device__ __forceinline__ void ln_store3(__nv_bfloat16* dh, __nv_bfloat16* dl, int lane,
                                          float v0, float v1, float v2) {
    __nv_bfloat16 h, l;
    split1(v0, h, l); dh[lane] = h;      dl[lane] = l;
    split1(v1, h, l); dh[lane + 32] = h; dl[lane + 32] = l;
    split1(v2, h, l); dh[lane + 64] = h; dl[lane + 64] = l;
}
__global__ void __launch_bounds__(128) ln_part_kernel(const float* __restrict__ src,
                                                      __nv_bfloat16* __restrict__ dh,
                                                      __nv_bfloat16* __restrict__ dl,
                                                      const float* __restrict__ gg,
                                                      const float* __restrict__ be,
                                                      int shift) {
    int warp = threadIdx.x >> 5, lane = threadIdx.x & 31;
    int gidx = blockIdx.x * 4 + warp;
    int bw = gidx / 49, nn = gidx - bw * 49;
    int b = bw >> 8, wy = (bw >> 4) & 15, wx = bw & 15;
    int iy = nn / 7, ix = nn - iy * 7;
    int ys = wy * 7 + iy + shift; if (ys >= H2) ys -= H2;
    int xs = wx * 7 + ix + shift; if (xs >= H2) xs -= H2;
    const float* sp = src + ((size_t)b * LTOK + ys * H2 + xs) * C2;
    float v0 = sp[lane], v1 = sp[lane + 32], v2 = sp[lane + 64];
    float mean = warp_sum(v0 + v1 + v2) * (1.f / 96.f);
    float d0 = v0 - mean, d1 = v1 - mean, d2 = v2 - mean;
    float var = warp_sum(d0*d0 + d1*d1 + d2*d2) * (1.f / 96.f);
    float inv = rsqrtf(var + 1e-5f);
    ln_store3(dh + (size_t)gidx * C2, dl + (size_t)gidx * C2, lane,
              d0 * inv * gg[lane] + be[lane],
              d1 * inv * gg[lane + 32] + be[lane + 32],
              d2 * inv * gg[lane + 64] + be[lane + 64]);
}
__global__ void __launch_bounds__(128) ln_plain_kernel(const float* __restrict__ src,
                                                       __nv_bfloat16* __restrict__ dh,
                                                       __nv_bfloat16* __restrict__ dl,
                                                       const float* __restrict__ gg,
                                                       const float* __restrict__ be) {
    int warp = threadIdx.x >> 5, lane = threadIdx.x & 31;
    size_t gidx = (size_t)blockIdx.x * 4 + warp;
    const float* sp = src + gidx * C2;
    float v0 = sp[lane], v1 = sp[lane + 32], v2 = sp[lane + 64];
    float mean = warp_sum(v0 + v1 + v2) * (1.f / 96.f);
    float d0 = v0 - mean, d1 = v1 - mean, d2 = v2 - mean;
    float var = warp_sum(d0*d0 + d1*d1 + d2*d2) * (1.f / 96.f);
    float inv = rsqrtf(var + 1e-5f);
    ln_store3(dh + gidx * C2, dl + gidx * C2, lane,
              d0 * inv * gg[lane] + be[lane],
              d1 * inv * gg[lane + 32] + be[lane + 32],
              d2 * inv * gg[lane + 64] + be[lane + 64]);
}

// ---------------- window attention -------------------------------------------
__global__ void __launch_bounds__(128) attn_kernel(const float* __restrict__ qkv,
                                                   const float* __restrict__ rel,
                                                   __nv_bfloat16* __restrict__ outh,
                                                   __nv_bfloat16* __restrict__ outl,
                                                   int shifted) {
    __shared__ float sq[2*784], sk[2*784], sv[2*784], srel[2*169];
    __shared__ int slbl[49];
    const int bw = blockIdx.x, h0 = blockIdx.y * 2;
    const int tid = threadIdx.x;

    for (int i = tid; i < 2 * 784; i += 128) {
        int hh = i / 784, idx = i - hh * 784;
        int h = h0 + hh;
        sq[i] = qkv[(((size_t)(bw * 3 + 0) * 6 + h)) * 784 + idx];
        sk[i] = qkv[(((size_t)(bw * 3 + 1) * 6 + h)) * 784 + idx];
        sv[i] = qkv[(((size_t)(bw * 3 + 2) * 6 + h)) * 784 + idx];
    }
    for (int i = tid; i < 2 * 169; i += 128) {
        int hh = i / 169, idx = i - hh * 169;
        srel[i] = rel[idx * 6 + h0 + hh];
    }
    if (tid < 49) {
        if (shifted) {
            int wy = (bw >> 4) & 15, wx = bw & 15;
            int yy = wy * 7 + tid / 7, xx = wx * 7 + tid % 7;
            int ry = (yy < 105) ? 0 : ((yy < 109) ? 1 : 2);
            int rx = (xx < 105) ? 0 : ((xx < 109) ? 1 : 2);
            slbl[tid] = ry * 3 + rx;
        } else slbl[tid] = 0;
    }
    __syncthreads();

    const int h2 = tid >> 6, n = tid & 63;
    if (n < 49) {
        const float* qh = sq + h2 * 784;
        const float* kh = sk + h2 * 784;
        const float* vh = sv + h2 * 784;
        const float* rh = srel + h2 * 169;
        const int iy = n / 7, ix = n - iy * 7;
        float4 q0 = *(const float4*)&qh[n*16+0];
        float4 q1 = *(const float4*)&qh[n*16+4];
        float4 q2 = *(const float4*)&qh[n*16+8];
        float4 q3 = *(const float4*)&qh[n*16+12];
        const int mylbl = slbl[n];
        float s[49];
        float mx = -1e30f;
        #pragma unroll
        for (int m = 0; m < 49; m++) {
            int jy = m / 7, jx = m - jy * 7;
            float4 k0 = *(const float4*)&kh[m*16+0];
            float4 k1 = *(const float4*)&kh[m*16+4];
            float4 k2 = *(const float4*)&kh[m*16+8];
            float4 k3 = *(const float4*)&kh[m*16+12];
            float d = q0.x*k0.x+q0.y*k0.y+q0.z*k0.z+q0.w*k0.w
                    + q1.x*k1.x+q1.y*k1.y+q1.z*k1.z+q1.w*k1.w
                    + q2.x*k2.x+q2.y*k2.y+q2.z*k2.z+q2.w*k2.w
                    + q3.x*k3.x+q3.y*k3.y+q3.z*k3.z+q3.w*k3.w;
            d += rh[(iy - jy + 6) * 13 + (ix - jx + 6)];
            if (shifted && slbl[m] != mylbl) d -= 100.f;
            s[m] = d;
            mx = fmaxf(mx, d);
        }
        float sum = 0.f;
        #pragma unroll
        for (int m = 0; m < 49; m++) {
            float e = __expf(s[m] - mx);
            s[m] = e;
            sum += e;
        }
        float inv = 1.f / sum;
        float o[16];
        #pragma unroll
        for (int d = 0; d < 16; d++) o[d] = 0.f;
        #pragma unroll
        for (int m = 0; m < 49; m++) {
            float p = s[m] * inv;
            float4 v0 = *(const float4*)&vh[m*16+0];
            float4 v1 = *(const float4*)&vh[m*16+4];
            float4 v2 = *(const float4*)&vh[m*16+8];
            float4 v3 = *(const float4*)&vh[m*16+12];
            o[0]+=p*v0.x; o[1]+=p*v0.y; o[2]+=p*v0.z; o[3]+=p*v0.w;
            o[4]+=p*v1.x; o[5]+=p*v1.y; o[6]+=p*v1.z; o[7]+=p*v1.w;
            o[8]+=p*v2.x; o[9]+=p*v2.y; o[10]+=p*v2.z; o[11]+=p*v2.w;
            o[12]+=p*v3.x; o[13]+=p*v3.y; o[14]+=p*v3.z; o[15]+=p*v3.w;
        }
        uint32_t uh[8], ul[8];
        #pragma unroll
        for (int d = 0; d < 8; d++) split2(o[2*d], o[2*d+1], uh[d], ul[d]);
        size_t o0 = ((size_t)bw * 49 + n) * C2 + (h0 + h2) * 16;
        ((uint4*)(outh + o0))[0] = make_uint4(uh[0], uh[1], uh[2], uh[3]);
        ((uint4*)(outh + o0))[1] = make_uint4(uh[4], uh[5], uh[6], uh[7]);
        ((uint4*)(outl + o0))[0] = make_uint4(ul[0], ul[1], ul[2], ul[3]);
        ((uint4*)(outl + o0))[1] = make_uint4(ul[4], ul[5], ul[6], ul[7]);
    }
}

// ---------------- launch -----------------------------------------------------
extern "C" void kernel_launch(void* const* d_in, const int* in_sizes, int n_in,
                              void* d_out, int out_size) {
    (void)in_sizes; (void)n_in; (void)out_size;
    const float* x     = (const float*)d_in[0];
    const float* up_w  = (const float*)d_in[1];
    const float* up_b  = (const float*)d_in[2];
    const float* bn_g  = (const float*)d_in[3];
    const float* bn_b  = (const float*)d_in[4];
    const float* bn_m  = (const float*)d_in[5];
    const float* bn_v  = (const float*)d_in[6];
    const float* n1g   = (const float*)d_in[7];
    const float* n1b   = (const float*)d_in[8];
    const float* qkvw  = (const float*)d_in[9];
    const float* qkvb  = (const float*)d_in[10];
    const float* projw = (const float*)d_in[11];
    const float* projb = (const float*)d_in[12];
    const float* rel   = (const float*)d_in[13];
    const float* n2g   = (const float*)d_in[14];
    const float* n2b   = (const float*)d_in[15];
    const float* f1w   = (const float*)d_in[16];
    const float* f1b   = (const float*)d_in[17];
    const float* f2w   = (const float*)d_in[18];
    const float* f2b   = (const float*)d_in[19];
    const float* outw  = (const float*)d_in[20];
    const float* outb  = (const float*)d_in[21];
    float* out = (float*)d_out;

    float *bX, *bQ, *scl, *sft;
    __nv_bfloat16 *bWh, *bWl, *bAh, *bAl, *bHh, *bHl, *wh, *wl;
    cudaGetSymbolAddress((void**)&bX,  d_bufX);
    cudaGetSymbolAddress((void**)&bQ,  d_bufQ);
    cudaGetSymbolAddress((void**)&bWh, d_bWh);
    cudaGetSymbolAddress((void**)&bWl, d_bWl);
    cudaGetSymbolAddress((void**)&bAh, d_bAh);
    cudaGetSymbolAddress((void**)&bAl, d_bAl);
    cudaGetSymbolAddress((void**)&bHh, d_bHh);
    cudaGetSymbolAddress((void**)&bHl, d_bHl);
    cudaGetSymbolAddress((void**)&wh,  d_wh);
    cudaGetSymbolAddress((void**)&wl,  d_wl);
    cudaGetSymbolAddress((void**)&scl, d_cscale);
    cudaGetSymbolAddress((void**)&sft, d_cshift);

    cudaFuncSetAttribute(mma_gemm_f<ALConv,   StConv>, cudaFuncAttributeMaxDynamicSharedMemorySize, SMEM_BYTES);
    cudaFuncSetAttribute(mma_gemm_f<ALDirect, StOut>,  cudaFuncAttributeMaxDynamicSharedMemorySize, SMEM_BYTES);
    cudaFuncSetAttribute(mma_gemm_p<StQKV>,  cudaFuncAttributeMaxDynamicSharedMemorySize, SMEM_BYTES);
    cudaFuncSetAttribute(mma_gemm_p<StProj>, cudaFuncAttributeMaxDynamicSharedMemorySize, SMEM_BYTES);
    cudaFuncSetAttribute(mma_gemm_p<StGelu>, cudaFuncAttributeMaxDynamicSharedMemorySize, SMEM_BYTES);
    cudaFuncSetAttribute(mma_gemm_p<StFC2>,  cudaFuncAttributeMaxDynamicSharedMemorySize, SMEM_BYTES);

    prep_conv<<<64, 256>>>(up_w, up_b, bn_g, bn_b, bn_m, bn_v);
    prep_w<<<221, 512>>>(qkvw, projw, f1w, f2w, outw);

    {   // fused 4-parity conv: blockIdx.z = parity
        ALConv al; al.in = x;
        StConv st; st.out = bX; st.scale = scl; st.shift = sft;
        mma_gemm_f<<<dim3(196, 1, 4), 256, SMEM_BYTES>>>(al, st, wh + OFF_WC, wl + OFF_WC,
                                                         96, 768, 96 * 768);
    }

    for (int i = 0; i < 2; i++) {
        int sh = i ? 3 : 0;
        ln_part_kernel<<<25088, 128>>>(bX, bWh, bWl, n1g + i * 96, n1b + i * 96, sh);

        { StQKV st; st.out = bQ; st.bias = qkvb + i * 288;
          mma_gemm_p<<<dim3(784, 3), 256, SMEM_BYTES>>>(bWh, bWl, st,
              wh + OFF_QKV + (size_t)i * 27648, wl + OFF_QKV + (size_t)i * 27648, 288, 96); }

        attn_kernel<<<dim3(2048, 3), 128>>>(bQ, rel + (size_t)i * 169 * 6, bAh, bAl, sh);

        { StProj st; st.out = bX; st.bias = projb + i * 96; st.shift = sh;
          mma_gemm_p<<<dim3(784, 1), 256, SMEM_BYTES>>>(bAh, bAl, st,
              wh + OFF_PROJ + (size_t)i * 9216, wl + OFF_PROJ + (size_t)i * 9216, 96, 96); }

        ln_plain_kernel<<<25088, 128>>>(bX, bWh, bWl, n2g + i * 96, n2b + i * 96);

        { StGelu st; st.outh = bHh; st.outl = bHl; st.bias = f1b + i * HID;
          mma_gemm_p<<<dim3(784, 4), 256, SMEM_BYTES>>>(bWh, bWl, st,
              wh + OFF_F1 + (size_t)i * 36864, wl + OFF_F1 + (size_t)i * 36864, HID, 96); }

        { StFC2 st; st.out = bX; st.bias = f2b + i * 96;
          mma_gemm_p<<<dim3(784, 1), 256, SMEM_BYTES>>>(bHh, bHl, st,
              wh + OFF_F2 + (size_t)i * 36864, wl + OFF_F2 + (size_t)i * 36864, 96, 384); }
    }

    { ALDirect al; al.A = bX; al.K = 96;
      StOut st; st.out = out; st.bias = outb;
      mma_gemm_f<<<dim3(784, 1, 1), 256, SMEM_BYTES>>>(al, st, wh + OFF_OUT, wl + OFF_OUT,
                                                       48, 96, 0); }
}

// round 12
// speedup vs baseline: 1.4869x; 1.1121x over previous
#include <cuda_runtime.h>
#include <cuda_bf16.h>
#include <math.h>
#include <stdint.h>

#define CB 8
#define C2 96
#define H2 112
#define LTOK 12544
#define NWB 2048
#define HID 384

#define SROW 104               // smem row pitch (halves) for 96-K stage, conflict-free ldmatrix
#define PS_A 6656              // 64*104 halves per A plane
#define PS_B 9984              // 96*104 halves per B plane
#define SMEM_BYTES ((2*PS_A + 2*PS_B) * 2)   // 66560 bytes -> 2 CTAs/SM

// weight arena offsets (elements)
#define OFF_WC   0
#define OFF_QKV  294912
#define OFF_PROJ 350208
#define OFF_F1   368640
#define OFF_F2   442368
#define OFF_OUT  516096
#define TOTW     520704

__device__ float d_bufX[CB*LTOK*C2];
__device__ float d_bufQ[NWB*3*6*49*16];
__device__ __nv_bfloat16 d_bWh[CB*LTOK*C2], d_bWl[CB*LTOK*C2];
__device__ __nv_bfloat16 d_bAh[CB*LTOK*C2], d_bAl[CB*LTOK*C2];
__device__ __nv_bfloat16 d_bHh[CB*LTOK*HID], d_bHl[CB*LTOK*HID];
__device__ __nv_bfloat16 d_wh[TOTW], d_wl[TOTW];
__device__ float d_cscale[96];
__device__ float d_cshift[96];

// ---------------- helpers ----------------
__device__ __forceinline__ uint32_t smem_u32(const void* p) {
    uint32_t a;
    asm("{ .reg .u64 t; cvta.to.shared.u64 t, %1; cvt.u32.u64 %0, t; }" : "=r"(a) : "l"(p));
    return a;
}
__device__ __forceinline__ void ldm_x4(uint32_t* r, uint32_t addr) {
    asm volatile("ldmatrix.sync.aligned.m8n8.x4.shared.b16 {%0,%1,%2,%3}, [%4];"
        : "=r"(r[0]), "=r"(r[1]), "=r"(r[2]), "=r"(r[3]) : "r"(addr));
}
__device__ __forceinline__ void mma_bf16(float* c, const uint32_t* a, const uint32_t* b) {
    asm volatile("mma.sync.aligned.m16n8k16.row.col.f32.bf16.bf16.f32 "
        "{%0,%1,%2,%3}, {%4,%5,%6,%7}, {%8,%9}, {%0,%1,%2,%3};"
        : "+f"(c[0]), "+f"(c[1]), "+f"(c[2]), "+f"(c[3])
        : "r"(a[0]), "r"(a[1]), "r"(a[2]), "r"(a[3]), "r"(b[0]), "r"(b[1]));
}
__device__ __forceinline__ void cpa16(uint32_t d, const void* g) {
    asm volatile("cp.async.ca.shared.global [%0], [%1], 16;" :: "r"(d), "l"(g) : "memory");
}
#define CP_COMMIT() asm volatile("cp.async.commit_group;" ::: "memory")
#define CP_WAIT0()  asm volatile("cp.async.wait_group 0;" ::: "memory")

__device__ __forceinline__ void split1(float x, __nv_bfloat16& h, __nv_bfloat16& l) {
    h = __float2bfloat16_rn(x);
    l = __float2bfloat16_rn(x - __bfloat162float(h));
}
__device__ __forceinline__ void split2(float x, float y, uint32_t& h, uint32_t& l) {
    __nv_bfloat16 hx, lx, hy, ly;
    split1(x, hx, lx); split1(y, hy, ly);
    h = ((uint32_t)__bfloat16_as_ushort(hy) << 16) | (uint32_t)__bfloat16_as_ushort(hx);
    l = ((uint32_t)__bfloat16_as_ushort(ly) << 16) | (uint32_t)__bfloat16_as_ushort(lx);
}
__device__ __forceinline__ void split4(float4 a, uint2& h, uint2& l) {
    split2(a.x, a.y, h.x, l.x);
    split2(a.z, a.w, h.y, l.y);
}

// ---------------- prep ----------------
__global__ void prep_conv(const float* __restrict__ up_w, const float* __restrict__ up_b,
                          const float* __restrict__ bn_g, const float* __restrict__ bn_b,
                          const float* __restrict__ bn_m, const float* __restrict__ bn_v) {
    int tid = blockIdx.x * blockDim.x + threadIdx.x;
    if (tid < 96) {
        float s = bn_g[tid] * rsqrtf(bn_v[tid] + 1e-5f);
        d_cscale[tid] = s;
        d_cshift[tid] = (up_b[tid] - bn_m[tid]) * s + bn_b[tid];
    }
    int total = 4 * 96 * 192;
    for (int idx = tid; idx < total; idx += gridDim.x * blockDim.x) {
        int p  = idx / (96 * 192);
        int r  = idx % (96 * 192);
        int co = r / 192, ci = r % 192;
        int py = p >> 1, px = p & 1;
        const float* w = up_w + ((size_t)co * 192 + ci) * 9;
        float cs[3][2];
        #pragma unroll
        for (int ky = 0; ky < 3; ky++) {
            float w0 = w[ky*3], w1 = w[ky*3+1], w2 = w[ky*3+2];
            cs[ky][0] = (px == 0) ? w0 : (w0 + w1);
            cs[ky][1] = (px == 0) ? (w1 + w2) : w2;
        }
        size_t dst = (size_t)OFF_WC + ((size_t)p * 96 + co) * 768 + ci * 4;
        float v[4];
        #pragma unroll
        for (int b2 = 0; b2 < 2; b2++) {
            v[b2]     = (py == 0) ? cs[0][b2] : (cs[0][b2] + cs[1][b2]);
            v[2 + b2] = (py == 0) ? (cs[1][b2] + cs[2][b2]) : cs[2][b2];
        }
        #pragma unroll
        for (int j = 0; j < 4; j++) {
            __nv_bfloat16 h, l;
            split1(v[j], h, l);
            d_wh[dst + j] = h; d_wl[dst + j] = l;
        }
    }
}

__global__ void prep_w(const float* __restrict__ qkvw, const float* __restrict__ projw,
                       const float* __restrict__ f1w,  const float* __restrict__ f2w,
                       const float* __restrict__ outw) {
    int tid = blockIdx.x * blockDim.x + threadIdx.x;
    int total = TOTW - OFF_QKV;
    for (int idx = tid; idx < total; idx += gridDim.x * blockDim.x) {
        float v; size_t dst = OFF_QKV + idx;
        int r = idx;
        if (r < 55296)                 v = qkvw[r];
        else if ((r -= 55296) < 18432) v = projw[r];
        else if ((r -= 18432) < 73728) v = f1w[r];
        else if ((r -= 73728) < 73728) v = f2w[r];
        else                           v = outw[r - 73728];
        __nv_bfloat16 h, l;
        split1(v, h, l);
        d_wh[dst] = h; d_wl[dst] = l;
    }
}

// ---------------- float-A loaders ----------
struct ALDirect {
    const float* A; int K;
    struct Ctx { const float* p; };
    __device__ Ctx prep(int m) const { Ctx c; c.p = A + (size_t)m * K; return c; }
    __device__ float4 load(const Ctx& c, int k) const { return *(const float4*)(c.p + k); }
};
struct ALConv {
    const float* in;
    struct Ctx { const float* base; int o0, o1, o2, o3; };
    __device__ Ctx prep(int m) const {
        int py = blockIdx.z >> 1, px = blockIdx.z & 1;
        int b = m / 3136, r = m - b * 3136;
        int ty = r / 56, tx = r - ty * 56;
        int r0 = ty - 1 + py, r1 = r0 + 1;
        int c0 = tx - 1 + px, c1 = c0 + 1;
        bool r0v = (unsigned)r0 < 56u, r1v = (unsigned)r1 < 56u;
        bool c0v = (unsigned)c0 < 56u, c1v = (unsigned)c1 < 56u;
        Ctx c;
        c.base = in + (size_t)b * 192 * 3136;
        c.o0 = (r0v && c0v) ? r0 * 56 + c0 : -1;
        c.o1 = (r0v && c1v) ? r0 * 56 + c1 : -1;
        c.o2 = (r1v && c0v) ? r1 * 56 + c0 : -1;
        c.o3 = (r1v && c1v) ? r1 * 56 + c1 : -1;
        return c;
    }
    __device__ float4 load(const Ctx& c, int k) const {
        const float* p = c.base + (size_t)(k >> 2) * 3136;
        float4 v;
        v.x = (c.o0 >= 0) ? p[c.o0] : 0.f;
        v.y = (c.o1 >= 0) ? p[c.o1] : 0.f;
        v.z = (c.o2 >= 0) ? p[c.o2] : 0.f;
        v.w = (c.o3 >= 0) ? p[c.o3] : 0.f;
        return v;
    }
};

// ---------------- epilogues --------------------------------------------------
struct StConv {
    float* out; const float* scale; const float* shift;
    __device__ void store(int m, int n, float v) const {
        int py = blockIdx.z >> 1, px = blockIdx.z & 1;
        v = fmaxf(v * scale[n] + shift[n], 0.f);
        int b = m / 3136, r = m - b * 3136;
        int ty = r / 56, tx = r - ty * 56;
        int y = 2 * ty + py, x = 2 * tx + px;
        out[((size_t)b * LTOK + y * H2 + x) * C2 + n] = v;
    }
};
struct StQKV {
    float* out; const float* bias;
    __device__ void store(int m, int n, float v) const {
        v += bias[n];
        int s3 = n / 96, rem = n - s3 * 96;
        int h = rem >> 4, d = rem & 15;
        if (s3 == 0) v *= 0.25f;
        int bw = m / 49, nn = m - bw * 49;
        out[(((size_t)(bw * 3 + s3) * 6 + h) * 49 + nn) * 16 + d] = v;
    }
};
struct StProj {
    float* out; const float* bias; int shift;
    __device__ void store(int m, int n, float v) const {
        int bw = m / 49, nn = m - bw * 49;
        int b = bw >> 8, wy = (bw >> 4) & 15, wx = bw & 15;
        int iy = nn / 7, ix = nn - iy * 7;
        int y = wy * 7 + iy + shift; if (y >= H2) y -= H2;
        int x = wx * 7 + ix + shift; if (x >= H2) x -= H2;
        out[((size_t)b * LTOK + y * H2 + x) * C2 + n] += v + bias[n];
    }
};
struct StGelu {
    __nv_bfloat16* outh; __nv_bfloat16* outl; const float* bias;
    __device__ void store(int m, int n, float v) const {
        v += bias[n];
        v = 0.5f * v * (1.0f + erff(v * 0.70710678118654752f));
        __nv_bfloat16 h, l;
        split1(v, h, l);
        size_t o = (size_t)m * HID + n;
        outh[o] = h; outl[o] = l;
    }
};
struct StFC2 {
    float* out; const float* bias;
    __device__ void store(int m, int n, float v) const {
        out[(size_t)m * C2 + n] += v + bias[n];
    }
};
struct StOut {
    float* out; const float* bias;
    __device__ void store(int m, int n, float v) const {
        v = fmaxf(v + bias[n], 0.f);
        int b = m / LTOK, pix = m - b * LTOK;
        out[((size_t)b * 48 + n) * LTOK + pix] = v;
    }
};

// ---------------- 96-K MMA stage (M=64, N=96, 8 warps 4m x 2n) ---------------
__device__ __forceinline__ void mma_stage96(uint32_t sbase, uint32_t aoff, uint32_t boff,
                                            float (&acc)[6][4]) {
    const uint32_t uAh = sbase, uAl = sbase + PS_A * 2;
    const uint32_t uBh = sbase + 2 * PS_A * 2, uBl = sbase + (2 * PS_A + PS_B) * 2;
    #pragma unroll
    for (int ks = 0; ks < 96; ks += 16) {
        uint32_t Ah[4], Al[4];
        ldm_x4(Ah, uAh + (aoff + ks) * 2);
        ldm_x4(Al, uAl + (aoff + ks) * 2);
        #pragma unroll
        for (int p = 0; p < 3; p++) {
            uint32_t bh[4], bl[4];
            ldm_x4(bh, uBh + (boff + p * 16 * SROW + ks) * 2);
            mma_bf16(acc[2*p],   Ah, bh);
            mma_bf16(acc[2*p+1], Ah, bh + 2);
            mma_bf16(acc[2*p],   Al, bh);
            mma_bf16(acc[2*p+1], Al, bh + 2);
            ldm_x4(bl, uBl + (boff + p * 16 * SROW + ks) * 2);
            mma_bf16(acc[2*p],   Ah, bl);
            mma_bf16(acc[2*p+1], Ah, bl + 2);
        }
    }
}

#define MMA_DECL \
    const int tid = threadIdx.x; \
    const int wid = tid >> 5, lane = tid & 31; \
    const int wm = wid & 3, wn = wid >> 2; \
    const int m0 = blockIdx.x << 6; \
    const int n0 = blockIdx.y * 96; \
    float acc[6][4]; \
    _Pragma("unroll") for (int ni = 0; ni < 6; ni++) \
    _Pragma("unroll") for (int r = 0; r < 4; r++) acc[ni][r] = 0.f; \
    const uint32_t sbase = smem_u32(smx); \
    const uint32_t aoff = (uint32_t)((wm * 16 + (lane & 15)) * SROW + (lane >> 4) * 8); \
    const uint32_t boff = (uint32_t)((wn * 48 + (lane & 7) + ((lane >> 4) << 3)) * SROW + ((lane >> 3) & 1) * 8);

#define MMA_EPI \
    _Pragma("unroll") for (int ni = 0; ni < 6; ni++) \
    _Pragma("unroll") for (int r = 0; r < 4; r++) { \
        int m = m0 + wm * 16 + (lane >> 2) + ((r >> 1) << 3); \
        int n = n0 + wn * 48 + ni * 8 + ((lane & 3) << 1) + (r & 1); \
        if (n < Nt) st.store(m, n, acc[ni][r]); \
    }

// ---------------- plane-A GEMM (K multiple of 96) ----------------------------
template<class ST>
__global__ void __launch_bounds__(256, 2) mma_gemm_p(
        const __nv_bfloat16* __restrict__ Ahp, const __nv_bfloat16* __restrict__ Alp,
        ST st, const __nv_bfloat16* __restrict__ Bh, const __nv_bfloat16* __restrict__ Bl,
        int Nt, int K) {
    extern __shared__ uint16_t smx[];
    MMA_DECL

    // A loader: 256 threads = 64 rows x 2 planes x 2 k-halves (48h each)
    const int arow = tid & 63, apl = (tid >> 6) & 1, ahalf = tid >> 7;
    const uint16_t* gA = (const uint16_t*)(apl ? Alp : Ahp) + (size_t)(m0 + arow) * K + ahalf * 48;
    const uint32_t dA = sbase + (uint32_t)(apl * PS_A + arow * SROW + ahalf * 48) * 2;
    // B loader: threads < 192 = 96 rows x 2 planes, 96h each
    const bool bact = tid < 192;
    const int brow = bact ? (tid < 96 ? tid : tid - 96) : 0;
    const int bpl = (tid >= 96) ? 1 : 0;
    const uint16_t* gB = (const uint16_t*)(bpl ? Bl : Bh) + (size_t)(n0 + brow) * K;
    const uint32_t dB = sbase + (uint32_t)(2 * PS_A + bpl * PS_B + brow * SROW) * 2;

    const int nst = K / 96;
    for (int kc = 0; kc < nst; kc++) {
        const int kb = kc * 96;
        if (kc > 0) __syncthreads();
        #pragma unroll
        for (int j = 0; j < 6; j++) cpa16(dA + j * 16, gA + kb + j * 8);
        if (bact) {
            #pragma unroll
            for (int j = 0; j < 12; j++) cpa16(dB + j * 16, gB + kb + j * 8);
        }
        CP_COMMIT();
        CP_WAIT0();
        __syncthreads();
        mma_stage96(sbase, aoff, boff, acc);
    }
    MMA_EPI
}

// ---------------- float-A GEMM (conv gather / out) ---------------------------
template<class AL, class ST>
__global__ void __launch_bounds__(256, 2) mma_gemm_f(
        AL al, ST st, const __nv_bfloat16* __restrict__ Bh0, const __nv_bfloat16* __restrict__ Bl0,
        int Nt, int K, int wstride) {
    extern __shared__ uint16_t smx[];
    const __nv_bfloat16* Bh = Bh0 + (size_t)blockIdx.z * wstride;
    const __nv_bfloat16* Bl = Bl0 + (size_t)blockIdx.z * wstride;
    MMA_DECL

    // A: 64 rows x 4 quarters (24 floats each)
    const int arow = tid & 63, aq = tid >> 6;
    typename AL::Ctx ctx = al.prep(m0 + arow);
    const uint32_t dAq = (uint32_t)(arow * SROW + aq * 24) * 2;
    const bool bact = tid < 192;
    const int brow = bact ? (tid < 96 ? tid : tid - 96) : 0;
    const int bpl = (tid >= 96) ? 1 : 0;
    int brc = brow; if (n0 + brc >= Nt) brc = Nt - 1 - n0;
    const uint16_t* gB = (const uint16_t*)(bpl ? Bl : Bh) + (size_t)(n0 + brc) * K;
    const uint32_t dB = sbase + (uint32_t)(2 * PS_A + bpl * PS_B + brow * SROW) * 2;

    const int nst = K / 96;
    for (int kc = 0; kc < nst; kc++) {
        const int kb = kc * 96;
        if (kc > 0) __syncthreads();
        if (bact) {
            #pragma unroll
            for (int j = 0; j < 12; j++) cpa16(dB + j * 16, gB + kb + j * 8);
        }
        CP_COMMIT();
        {
            uint32_t dAh = sbase + dAq;
            uint32_t dAl = dAh + PS_A * 2;
            #pragma unroll
            for (int j = 0; j < 6; j++) {
                float4 v = al.load(ctx, kb + aq * 24 + j * 4);
                uint2 h, l;
                split4(v, h, l);
                asm volatile("st.shared.v2.b32 [%0], {%1, %2};" :: "r"(dAh + j * 8), "r"(h.x), "r"(h.y));
                asm volatile("st.shared.v2.b32 [%0], {%1, %2};" :: "r"(dAl + j * 8), "r"(l.x), "r"(l.y));
            }
        }
        CP_WAIT0();
        __syncthreads();
        mma_stage96(sbase, aoff, boff, acc);
    }
    MMA_EPI
}

// ---------------- LayerNorm (writes bf16 planes) -----------------------------
__device__ __forceinline__ float warp_sum(float v) {
    #pragma unroll
    for (int o = 16; o; o >>= 1) v += __shfl_xor_sync(0xffffffffu, v, o);
    return v;
}
__device__ __forceinline__ void ln_store3(__nv_bfloat16* dh, __nv_bfloat16* dl, int lane,
                                          float v0, float v1, float v2) {
    __nv_bfloat16 h, l;
    split1(v0, h, l); dh[lane] = h;      dl[lane] = l;
    split1(v1, h, l); dh[lane + 32] = h; dl[lane + 32] = l;
    split1(v2, h, l); dh[lane + 64] = h; dl[lane + 64] = l;
}
__global__ void __launch_bounds__(128) ln_part_kernel(const float* __restrict__ src,
                                                      __nv_bfloat16* __restrict__ dh,
                                                      __nv_bfloat16* __restrict__ dl,
                                                      const float* __restrict__ gg,
                                                      const float* __restrict__ be,
                                                      int shift) {
    int warp = threadIdx.x >> 5, lane = threadIdx.x & 31;
    int gidx = blockIdx.x * 4 + warp;
    int bw = gidx / 49, nn = gidx - bw * 49;
    int b = bw >> 8, wy = (bw >> 4) & 15, wx = bw & 15;
    int iy = nn / 7, ix = nn - iy * 7;
    int ys = wy * 7 + iy + shift; if (ys >= H2) ys -= H2;
    int xs = wx * 7 + ix + shift; if (xs >= H2) xs -= H2;
    const float* sp = src + ((size_t)b * LTOK + ys * H2 + xs) * C2;
    float v0 = sp[lane], v1 = sp[lane + 32], v2 = sp[lane + 64];
    float mean = warp_sum(v0 + v1 + v2) * (1.f / 96.f);
    float d0 = v0 - mean, d1 = v1 - mean, d2 = v2 - mean;
    float var = warp_sum(d0*d0 + d1*d1 + d2*d2) * (1.f / 96.f);
    float inv = rsqrtf(var + 1e-5f);
    ln_store3(dh + (size_t)gidx * C2, dl + (size_t)gidx * C2, lane,
              d0 * inv * gg[lane] + be[lane],
              d1 * inv * gg[lane + 32] + be[lane + 32],
              d2 * inv * gg[lane + 64] + be[lane + 64]);
}
__global__ void __launch_bounds__(128) ln_plain_kernel(const float* __restrict__ src,
                                                       __nv_bfloat16* __restrict__ dh,
                                                       __nv_bfloat16* __restrict__ dl,
                                                       const float* __restrict__ gg,
                                                       const float* __restrict__ be) {
    int warp = threadIdx.x >> 5, lane = threadIdx.x & 31;
    size_t gidx = (size_t)blockIdx.x * 4 + warp;
    const float* sp = src + gidx * C2;
    float v0 = sp[lane], v1 = sp[lane + 32], v2 = sp[lane + 64];
    float mean = warp_sum(v0 + v1 + v2) * (1.f / 96.f);
    float d0 = v0 - mean, d1 = v1 - mean, d2 = v2 - mean;
    float var = warp_sum(d0*d0 + d1*d1 + d2*d2) * (1.f / 96.f);
    float inv = rsqrtf(var + 1e-5f);
    ln_store3(dh + gidx * C2, dl + gidx * C2, lane,
              d0 * inv * gg[lane] + be[lane],
              d1 * inv * gg[lane + 32] + be[lane + 32],
              d2 * inv * gg[lane + 64] + be[lane + 64]);
}

// ---------------- window attention -------------------------------------------
__global__ void __launch_bounds__(128) attn_kernel(const float* __restrict__ qkv,
                                                   const float* __restrict__ rel,
                                                   __nv_bfloat16* __restrict__ outh,
                                                   __nv_bfloat16* __restrict__ outl,
                                                   int shifted) {
    __shared__ float sq[2*784], sk[2*784], sv[2*784], srel[2*169];
    __shared__ int slbl[49];
    const int bw = blockIdx.x, h0 = blockIdx.y * 2;
    const int tid = threadIdx.x;

    for (int i = tid; i < 2 * 784; i += 128) {
        int hh = i / 784, idx = i - hh * 784;
        int h = h0 + hh;
        sq[i] = qkv[(((size_t)(bw * 3 + 0) * 6 + h)) * 784 + idx];
        sk[i] = qkv[(((size_t)(bw * 3 + 1) * 6 + h)) * 784 + idx];
        sv[i] = qkv[(((size_t)(bw * 3 + 2) * 6 + h)) * 784 + idx];
    }
    for (int i = tid; i < 2 * 169; i += 128) {
        int hh = i / 169, idx = i - hh * 169;
        srel[i] = rel[idx * 6 + h0 + hh];
    }
    if (tid < 49) {
        if (shifted) {
            int wy = (bw >> 4) & 15, wx = bw & 15;
            int yy = wy * 7 + tid / 7, xx = wx * 7 + tid % 7;
            int ry = (yy < 105) ? 0 : ((yy < 109) ? 1 : 2);
            int rx = (xx < 105) ? 0 : ((xx < 109) ? 1 : 2);
            slbl[tid] = ry * 3 + rx;
        } else slbl[tid] = 0;
    }
    __syncthreads();

    const int h2 = tid >> 6, n = tid & 63;
    if (n < 49) {
        const float* qh = sq + h2 * 784;
        const float* kh = sk + h2 * 784;
        const float* vh = sv + h2 * 784;
        const float* rh = srel + h2 * 169;
        const int iy = n / 7, ix = n - iy * 7;
        float4 q0 = *(const float4*)&qh[n*16+0];
        float4 q1 = *(const float4*)&qh[n*16+4];
        float4 q2 = *(const float4*)&qh[n*16+8];
        float4 q3 = *(const float4*)&qh[n*16+12];
        const int mylbl = slbl[n];
        float s[49];
        float mx = -1e30f;
        #pragma unroll
        for (int m = 0; m < 49; m++) {
            int jy = m / 7, jx = m - jy * 7;
            float4 k0 = *(const float4*)&kh[m*16+0];
            float4 k1 = *(const float4*)&kh[m*16+4];
            float4 k2 = *(const float4*)&kh[m*16+8];
            float4 k3 = *(const float4*)&kh[m*16+12];
            float d = q0.x*k0.x+q0.y*k0.y+q0.z*k0.z+q0.w*k0.w
                    + q1.x*k1.x+q1.y*k1.y+q1.z*k1.z+q1.w*k1.w
                    + q2.x*k2.x+q2.y*k2.y+q2.z*k2.z+q2.w*k2.w
                    + q3.x*k3.x+q3.y*k3.y+q3.z*k3.z+q3.w*k3.w;
            d += rh[(iy - jy + 6) * 13 + (ix - jx + 6)];
            if (shifted && slbl[m] != mylbl) d -= 100.f;
            s[m] = d;
            mx = fmaxf(mx, d);
        }
        float sum = 0.f;
        #pragma unroll
        for (int m = 0; m < 49; m++) {
            float e = __expf(s[m] - mx);
            s[m] = e;
            sum += e;
        }
        float inv = 1.f / sum;
        float o[16];
        #pragma unroll
        for (int d = 0; d < 16; d++) o[d] = 0.f;
        #pragma unroll
        for (int m = 0; m < 49; m++) {
            float p = s[m] * inv;
            float4 v0 = *(const float4*)&vh[m*16+0];
            float4 v1 = *(const float4*)&vh[m*16+4];
            float4 v2 = *(const float4*)&vh[m*16+8];
            float4 v3 = *(const float4*)&vh[m*16+12];
            o[0]+=p*v0.x; o[1]+=p*v0.y; o[2]+=p*v0.z; o[3]+=p*v0.w;
            o[4]+=p*v1.x; o[5]+=p*v1.y; o[6]+=p*v1.z; o[7]+=p*v1.w;
            o[8]+=p*v2.x; o[9]+=p*v2.y; o[10]+=p*v2.z; o[11]+=p*v2.w;
            o[12]+=p*v3.x; o[13]+=p*v3.y; o[14]+=p*v3.z; o[15]+=p*v3.w;
        }
        uint32_t uh[8], ul[8];
        #pragma unroll
        for (int d = 0; d < 8; d++) split2(o[2*d], o[2*d+1], uh[d], ul[d]);
        size_t o0 = ((size_t)bw * 49 + n) * C2 + (h0 + h2) * 16;
        ((uint4*)(outh + o0))[0] = make_uint4(uh[0], uh[1], uh[2], uh[3]);
        ((uint4*)(outh + o0))[1] = make_uint4(uh[4], uh[5], uh[6], uh[7]);
        ((uint4*)(outl + o0))[0] = make_uint4(ul[0], ul[1], ul[2], ul[3]);
        ((uint4*)(outl + o0))[1] = make_uint4(ul[4], ul[5], ul[6], ul[7]);
    }
}

// ---------------- launch -----------------------------------------------------
extern "C" void kernel_launch(void* const* d_in, const int* in_sizes, int n_in,
                              void* d_out, int out_size) {
    (void)in_sizes; (void)n_in; (void)out_size;
    const float* x     = (const float*)d_in[0];
    const float* up_w  = (const float*)d_in[1];
    const float* up_b  = (const float*)d_in[2];
    const float* bn_g  = (const float*)d_in[3];
    const float* bn_b  = (const float*)d_in[4];
    const float* bn_m  = (const float*)d_in[5];
    const float* bn_v  = (const float*)d_in[6];
    const float* n1g   = (const float*)d_in[7];
    const float* n1b   = (const float*)d_in[8];
    const float* qkvw  = (const float*)d_in[9];
    const float* qkvb  = (const float*)d_in[10];
    const float* projw = (const float*)d_in[11];
    const float* projb = (const float*)d_in[12];
    const float* rel   = (const float*)d_in[13];
    const float* n2g   = (const float*)d_in[14];
    const float* n2b   = (const float*)d_in[15];
    const float* f1w   = (const float*)d_in[16];
    const float* f1b   = (const float*)d_in[17];
    const float* f2w   = (const float*)d_in[18];
    const float* f2b   = (const float*)d_in[19];
    const float* outw  = (const float*)d_in[20];
    const float* outb  = (const float*)d_in[21];
    float* out = (float*)d_out;

    float *bX, *bQ, *scl, *sft;
    __nv_bfloat16 *bWh, *bWl, *bAh, *bAl, *bHh, *bHl, *wh, *wl;
    cudaGetSymbolAddress((void**)&bX,  d_bufX);
    cudaGetSymbolAddress((void**)&bQ,  d_bufQ);
    cudaGetSymbolAddress((void**)&bWh, d_bWh);
    cudaGetSymbolAddress((void**)&bWl, d_bWl);
    cudaGetSymbolAddress((void**)&bAh, d_bAh);
    cudaGetSymbolAddress((void**)&bAl, d_bAl);
    cudaGetSymbolAddress((void**)&bHh, d_bHh);
    cudaGetSymbolAddress((void**)&bHl, d_bHl);
    cudaGetSymbolAddress((void**)&wh,  d_wh);
    cudaGetSymbolAddress((void**)&wl,  d_wl);
    cudaGetSymbolAddress((void**)&scl, d_cscale);
    cudaGetSymbolAddress((void**)&sft, d_cshift);

    cudaFuncSetAttribute(mma_gemm_f<ALConv,   StConv>, cudaFuncAttributeMaxDynamicSharedMemorySize, SMEM_BYTES);
    cudaFuncSetAttribute(mma_gemm_f<ALDirect, StOut>,  cudaFuncAttributeMaxDynamicSharedMemorySize, SMEM_BYTES);
    cudaFuncSetAttribute(mma_gemm_p<StQKV>,  cudaFuncAttributeMaxDynamicSharedMemorySize, SMEM_BYTES);
    cudaFuncSetAttribute(mma_gemm_p<StProj>, cudaFuncAttributeMaxDynamicSharedMemorySize, SMEM_BYTES);
    cudaFuncSetAttribute(mma_gemm_p<StGelu>, cudaFuncAttributeMaxDynamicSharedMemorySize, SMEM_BYTES);
    cudaFuncSetAttribute(mma_gemm_p<StFC2>,  cudaFuncAttributeMaxDynamicSharedMemorySize, SMEM_BYTES);

    prep_conv<<<64, 256>>>(up_w, up_b, bn_g, bn_b, bn_m, bn_v);
    prep_w<<<221, 512>>>(qkvw, projw, f1w, f2w, outw);

    {   // fused 4-parity conv: blockIdx.z = parity
        ALConv al; al.in = x;
        StConv st; st.out = bX; st.scale = scl; st.shift = sft;
        mma_gemm_f<<<dim3(392, 1, 4), 256, SMEM_BYTES>>>(al, st, wh + OFF_WC, wl + OFF_WC,
                                                         96, 768, 96 * 768);
    }

    for (int i = 0; i < 2; i++) {
        int sh = i ? 3 : 0;
        ln_part_kernel<<<25088, 128>>>(bX, bWh, bWl, n1g + i * 96, n1b + i * 96, sh);

        { StQKV st; st.out = bQ; st.bias = qkvb + i * 288;
          mma_gemm_p<<<dim3(1568, 3), 256, SMEM_BYTES>>>(bWh, bWl, st,
              wh + OFF_QKV + (size_t)i * 27648, wl + OFF_QKV + (size_t)i * 27648, 288, 96); }

        attn_kernel<<<dim3(2048, 3), 128>>>(bQ, rel + (size_t)i * 169 * 6, bAh, bAl, sh);

        { StProj st; st.out = bX; st.bias = projb + i * 96; st.shift = sh;
          mma_gemm_p<<<dim3(1568, 1), 256, SMEM_BYTES>>>(bAh, bAl, st,
              wh + OFF_PROJ + (size_t)i * 9216, wl + OFF_PROJ + (size_t)i * 9216, 96, 96); }

        ln_plain_kernel<<<25088, 128>>>(bX, bWh, bWl, n2g + i * 96, n2b + i * 96);

        { StGelu st; st.outh = bHh; st.outl = bHl; st.bias = f1b + i * HID;
          mma_gemm_p<<<dim3(1568, 4), 256, SMEM_BYTES>>>(bWh, bWl, st,
              wh + OFF_F1 + (size_t)i * 36864, wl + OFF_F1 + (size_t)i * 36864, HID, 96); }

        { StFC2 st; st.out = bX; st.bias = f2b + i * 96;
          mma_gemm_p<<<dim3(1568, 1), 256, SMEM_BYTES>>>(bHh, bHl, st,
              wh + OFF_F2 + (size_t)i * 36864, wl + OFF_F2 + (size_t)i * 36864, 96, 384); }
    }

    { ALDirect al; al.A = bX; al.K = 96;
      StOut st; st.out = out; st.bias = outb;
      mma_gemm_f<<<dim3(1568, 1, 1), 256, SMEM_BYTES>>>(al, st, wh + OFF_OUT, wl + OFF_OUT,
                                                        48, 96, 0); }
}

// round 14
// speedup vs baseline: 2.5092x; 1.6875x over previous
#include <cuda_runtime.h>
#include <cuda_fp16.h>
#include <math.h>
#include <stdint.h>

#define CB 8
#define C2 96
#define H2 112
#define LTOK 12544
#define NWB 2048
#define HID 384

#define SROW 104               // smem row pitch in halves (208B rows, conflict-free ldmatrix)
#define AS_H (128*SROW)        // A tile halves
#define BS_H (96*SROW)         // B tile halves
#define SMEM_BYTES ((AS_H + BS_H) * 2)   // 46592 bytes -> 2 CTAs/SM

// weight arena offsets (elements)
#define OFF_WC   0
#define OFF_QKV  294912
#define OFF_PROJ 350208
#define OFF_F1   368640
#define OFF_F2   442368
#define OFF_OUT  516096
#define TOTW     520704

__device__ float d_bufX[CB*LTOK*C2];
__device__ float d_bufQ[NWB*3*6*49*16];
__device__ __half d_bW[CB*LTOK*C2];
__device__ __half d_bA[CB*LTOK*C2];
__device__ __half d_bH[CB*LTOK*HID];
__device__ __half d_wf[TOTW];
__device__ float d_cscale[96];
__device__ float d_cshift[96];

// ---------------- helpers ----------------
__device__ __forceinline__ uint32_t smem_u32(const void* p) {
    uint32_t a;
    asm("{ .reg .u64 t; cvta.to.shared.u64 t, %1; cvt.u32.u64 %0, t; }" : "=r"(a) : "l"(p));
    return a;
}
__device__ __forceinline__ void ldm_x4(uint32_t* r, uint32_t addr) {
    asm volatile("ldmatrix.sync.aligned.m8n8.x4.shared.b16 {%0,%1,%2,%3}, [%4];"
        : "=r"(r[0]), "=r"(r[1]), "=r"(r[2]), "=r"(r[3]) : "r"(addr));
}
__device__ __forceinline__ void ldm_x2(uint32_t* r, uint32_t addr) {
    asm volatile("ldmatrix.sync.aligned.m8n8.x2.shared.b16 {%0,%1}, [%2];"
        : "=r"(r[0]), "=r"(r[1]) : "r"(addr));
}
__device__ __forceinline__ void mma_f16(float* c, const uint32_t* a, const uint32_t* b) {
    asm volatile("mma.sync.aligned.m16n8k16.row.col.f32.f16.f16.f32 "
        "{%0,%1,%2,%3}, {%4,%5,%6,%7}, {%8,%9}, {%0,%1,%2,%3};"
        : "+f"(c[0]), "+f"(c[1]), "+f"(c[2]), "+f"(c[3])
        : "r"(a[0]), "r"(a[1]), "r"(a[2]), "r"(a[3]), "r"(b[0]), "r"(b[1]));
}
__device__ __forceinline__ void cpa16(uint32_t d, const void* g) {
    asm volatile("cp.async.ca.shared.global [%0], [%1], 16;" :: "r"(d), "l"(g) : "memory");
}
#define CP_COMMIT() asm volatile("cp.async.commit_group;" ::: "memory")
#define CP_WAIT0()  asm volatile("cp.async.wait_group 0;" ::: "memory")

__device__ __forceinline__ uint32_t pack2h(float x, float y) {
    __half2 h = __floats2half2_rn(x, y);
    return *(uint32_t*)&h;
}
__device__ __forceinline__ uint2 pack4h(float4 v) {
    uint2 r;
    r.x = pack2h(v.x, v.y);
    r.y = pack2h(v.z, v.w);
    return r;
}

// ---------------- prep ----------------
__global__ void prep_conv(const float* __restrict__ up_w, const float* __restrict__ up_b,
                          const float* __restrict__ bn_g, const float* __restrict__ bn_b,
                          const float* __restrict__ bn_m, const float* __restrict__ bn_v) {
    int tid = blockIdx.x * blockDim.x + threadIdx.x;
    if (tid < 96) {
        float s = bn_g[tid] * rsqrtf(bn_v[tid] + 1e-5f);
        d_cscale[tid] = s;
        d_cshift[tid] = (up_b[tid] - bn_m[tid]) * s + bn_b[tid];
    }
    int total = 4 * 96 * 192;
    for (int idx = tid; idx < total; idx += gridDim.x * blockDim.x) {
        int p  = idx / (96 * 192);
        int r  = idx % (96 * 192);
        int co = r / 192, ci = r % 192;
        int py = p >> 1, px = p & 1;
        const float* w = up_w + ((size_t)co * 192 + ci) * 9;
        float cs[3][2];
        #pragma unroll
        for (int ky = 0; ky < 3; ky++) {
            float w0 = w[ky*3], w1 = w[ky*3+1], w2 = w[ky*3+2];
            cs[ky][0] = (px == 0) ? w0 : (w0 + w1);
            cs[ky][1] = (px == 0) ? (w1 + w2) : w2;
        }
        size_t dst = (size_t)OFF_WC + ((size_t)p * 96 + co) * 768 + ci * 4;
        float v[4];
        #pragma unroll
        for (int b2 = 0; b2 < 2; b2++) {
            v[b2]     = (py == 0) ? cs[0][b2] : (cs[0][b2] + cs[1][b2]);
            v[2 + b2] = (py == 0) ? (cs[1][b2] + cs[2][b2]) : cs[2][b2];
        }
        #pragma unroll
        for (int j = 0; j < 4; j++) d_wf[dst + j] = __float2half_rn(v[j]);
    }
}

__global__ void prep_w(const float* __restrict__ qkvw, const float* __restrict__ projw,
                       const float* __restrict__ f1w,  const float* __restrict__ f2w,
                       const float* __restrict__ outw) {
    int tid = blockIdx.x * blockDim.x + threadIdx.x;
    int total = TOTW - OFF_QKV;
    for (int idx = tid; idx < total; idx += gridDim.x * blockDim.x) {
        float v; size_t dst = OFF_QKV + idx;
        int r = idx;
        if (r < 55296)                 v = qkvw[r];
        else if ((r -= 55296) < 18432) v = projw[r];
        else if ((r -= 18432) < 73728) v = f1w[r];
        else if ((r -= 73728) < 73728) v = f2w[r];
        else                           v = outw[r - 73728];
        d_wf[dst] = __float2half_rn(v);
    }
}

// ---------------- float-A loaders ----------
struct ALDirect {
    const float* A; int K;
    struct Ctx { const float* p; };
    __device__ Ctx prep(int m) const { Ctx c; c.p = A + (size_t)m * K; return c; }
    __device__ float4 load(const Ctx& c, int k) const { return *(const float4*)(c.p + k); }
};
struct ALConv {
    const float* in;
    struct Ctx { const float* base; int o0, o1, o2, o3; };
    __device__ Ctx prep(int m) const {
        int py = blockIdx.z >> 1, px = blockIdx.z & 1;
        int b = m / 3136, r = m - b * 3136;
        int ty = r / 56, tx = r - ty * 56;
        int r0 = ty - 1 + py, r1 = r0 + 1;
        int c0 = tx - 1 + px, c1 = c0 + 1;
        bool r0v = (unsigned)r0 < 56u, r1v = (unsigned)r1 < 56u;
        bool c0v = (unsigned)c0 < 56u, c1v = (unsigned)c1 < 56u;
        Ctx c;
        c.base = in + (size_t)b * 192 * 3136;
        c.o0 = (r0v && c0v) ? r0 * 56 + c0 : -1;
        c.o1 = (r0v && c1v) ? r0 * 56 + c1 : -1;
        c.o2 = (r1v && c0v) ? r1 * 56 + c0 : -1;
        c.o3 = (r1v && c1v) ? r1 * 56 + c1 : -1;
        return c;
    }
    __device__ float4 load(const Ctx& c, int k) const {
        const float* p = c.base + (size_t)(k >> 2) * 3136;
        float4 v;
        v.x = (c.o0 >= 0) ? p[c.o0] : 0.f;
        v.y = (c.o1 >= 0) ? p[c.o1] : 0.f;
        v.z = (c.o2 >= 0) ? p[c.o2] : 0.f;
        v.w = (c.o3 >= 0) ? p[c.o3] : 0.f;
        return v;
    }
};

// ---------------- epilogues --------------------------------------------------
struct StConv {
    float* out; const float* scale; const float* shift;
    __device__ void store(int m, int n, float v) const {
        int py = blockIdx.z >> 1, px = blockIdx.z & 1;
        v = fmaxf(v * scale[n] + shift[n], 0.f);
        int b = m / 3136, r = m - b * 3136;
        int ty = r / 56, tx = r - ty * 56;
        int y = 2 * ty + py, x = 2 * tx + px;
        out[((size_t)b * LTOK + y * H2 + x) * C2 + n] = v;
    }
};
struct StQKV {
    float* out; const float* bias;
    __device__ void store(int m, int n, float v) const {
        v += bias[n];
        int s3 = n / 96, rem = n - s3 * 96;
        int h = rem >> 4, d = rem & 15;
        if (s3 == 0) v *= 0.25f;
        int bw = m / 49, nn = m - bw * 49;
        out[(((size_t)(bw * 3 + s3) * 6 + h) * 49 + nn) * 16 + d] = v;
    }
};
struct StProj {
    float* out; const float* bias; int shift;
    __device__ void store(int m, int n, float v) const {
        int bw = m / 49, nn = m - bw * 49;
        int b = bw >> 8, wy = (bw >> 4) & 15, wx = bw & 15;
        int iy = nn / 7, ix = nn - iy * 7;
        int y = wy * 7 + iy + shift; if (y >= H2) y -= H2;
        int x = wx * 7 + ix + shift; if (x >= H2) x -= H2;
        out[((size_t)b * LTOK + y * H2 + x) * C2 + n] += v + bias[n];
    }
};
struct StGelu {
    __half* outp; const float* bias;
    __device__ void store(int m, int n, float v) const {
        v += bias[n];
        v = 0.5f * v * (1.0f + erff(v * 0.70710678118654752f));
        outp[(size_t)m * HID + n] = __float2half_rn(v);
    }
};
struct StFC2 {
    float* out; const float* bias;
    __device__ void store(int m, int n, float v) const {
        out[(size_t)m * C2 + n] += v + bias[n];
    }
};
struct StOut {
    float* out; const float* bias;
    __device__ void store(int m, int n, float v) const {
        v = fmaxf(v + bias[n], 0.f);
        int b = m / LTOK, pix = m - b * LTOK;
        out[((size_t)b * 48 + n) * LTOK + pix] = v;
    }
};

// ---------------- 96-K fp16 MMA stage (M=128, N=96, 8 warps 4m x 2n) ---------
__device__ __forceinline__ void mma_stage96(uint32_t uA, uint32_t uB,
                                            uint32_t aoff, uint32_t boff,
                                            float (&acc)[2][6][4]) {
    #pragma unroll
    for (int ks = 0; ks < 96; ks += 16) {
        uint32_t fA0[4], fA1[4];
        ldm_x4(fA0, uA + (aoff + ks) * 2);
        ldm_x4(fA1, uA + (aoff + 16 * SROW + ks) * 2);
        #pragma unroll
        for (int ni = 0; ni < 6; ni++) {
            uint32_t b[2];
            ldm_x2(b, uB + (boff + ni * 8 * SROW + ks) * 2);
            mma_f16(acc[0][ni], fA0, b);
            mma_f16(acc[1][ni], fA1, b);
        }
    }
}

#define MMA_DECL \
    const int tid = threadIdx.x; \
    const int wid = tid >> 5, lane = tid & 31; \
    const int wm = wid & 3, wn = wid >> 2; \
    const int m0 = blockIdx.x << 7; \
    const int n0 = blockIdx.y * 96; \
    float acc[2][6][4]; \
    _Pragma("unroll") for (int mi = 0; mi < 2; mi++) \
    _Pragma("unroll") for (int ni = 0; ni < 6; ni++) \
    _Pragma("unroll") for (int r = 0; r < 4; r++) acc[mi][ni][r] = 0.f; \
    const uint32_t uA = smem_u32(smx); \
    const uint32_t uB = uA + AS_H * 2; \
    const uint32_t aoff = (uint32_t)((wm * 32 + (lane & 15)) * SROW + (lane >> 4) * 8); \
    const uint32_t boff = (uint32_t)((wn * 48 + (lane & 7)) * SROW + ((lane >> 3) & 1) * 8);

#define MMA_EPI \
    _Pragma("unroll") for (int mi = 0; mi < 2; mi++) \
    _Pragma("unroll") for (int ni = 0; ni < 6; ni++) \
    _Pragma("unroll") for (int r = 0; r < 4; r++) { \
        int m = m0 + wm * 32 + mi * 16 + (lane >> 2) + ((r >> 1) << 3); \
        int n = n0 + wn * 48 + ni * 8 + ((lane & 3) << 1) + (r & 1); \
        if (n < Nt) st.store(m, n, acc[mi][ni][r]); \
    }

// ---------------- fp16-A GEMM (K multiple of 96) -----------------------------
template<class ST>
__global__ void __launch_bounds__(256, 2) mma_gemm_p(
        const __half* __restrict__ Ap, ST st, const __half* __restrict__ Bw,
        int Nt, int K) {
    extern __shared__ uint16_t smx[];
    MMA_DECL

    const int arow = tid & 127, ahalf = tid >> 7;
    const uint16_t* gA = (const uint16_t*)Ap + (size_t)(m0 + arow) * K + ahalf * 48;
    const uint32_t dA = uA + (uint32_t)(arow * SROW + ahalf * 48) * 2;
    const bool bact = tid < 192;
    const int brow = bact ? (tid >> 1) : 0;
    const int bhalf = tid & 1;
    int brc = brow; if (n0 + brc >= Nt) brc = Nt - 1 - n0;
    const uint16_t* gB = (const uint16_t*)Bw + (size_t)(n0 + brc) * K + bhalf * 48;
    const uint32_t dB = uB + (uint32_t)(brow * SROW + bhalf * 48) * 2;

    const int nst = K / 96;
    for (int kc = 0; kc < nst; kc++) {
        const int kb = kc * 96;
        if (kc > 0) __syncthreads();
        #pragma unroll
        for (int j = 0; j < 6; j++) cpa16(dA + j * 16, gA + kb + j * 8);
        if (bact) {
            #pragma unroll
            for (int j = 0; j < 6; j++) cpa16(dB + j * 16, gB + kb + j * 8);
        }
        CP_COMMIT();
        CP_WAIT0();
        __syncthreads();
        mma_stage96(uA, uB, aoff, boff, acc);
    }
    MMA_EPI
}

// ---------------- float-A GEMM (conv gather / out) ---------------------------
template<class AL, class ST>
__global__ void __launch_bounds__(256, 2) mma_gemm_f(
        AL al, ST st, const __half* __restrict__ Bw0,
        int Nt, int K, int wstride) {
    extern __shared__ uint16_t smx[];
    const __half* Bw = Bw0 + (size_t)blockIdx.z * wstride;
    MMA_DECL

    const int arow = tid & 127, ahalf = tid >> 7;
    typename AL::Ctx ctx = al.prep(m0 + arow);
    const uint32_t dA = uA + (uint32_t)(arow * SROW + ahalf * 48) * 2;
    const bool bact = tid < 192;
    const int brow = bact ? (tid >> 1) : 0;
    const int bhalf = tid & 1;
    int brc = brow; if (n0 + brc >= Nt) brc = Nt - 1 - n0;
    const uint16_t* gB = (const uint16_t*)Bw + (size_t)(n0 + brc) * K + bhalf * 48;
    const uint32_t dB = uB + (uint32_t)(brow * SROW + bhalf * 48) * 2;

    const int nst = K / 96;
    for (int kc = 0; kc < nst; kc++) {
        const int kb = kc * 96;
        if (kc > 0) __syncthreads();
        if (bact) {
            #pragma unroll
            for (int j = 0; j < 6; j++) cpa16(dB + j * 16, gB + kb + j * 8);
        }
        CP_COMMIT();
        #pragma unroll
        for (int j = 0; j < 6; j++) {
            float4 v0 = al.load(ctx, kb + ahalf * 48 + j * 8);
            float4 v1 = al.load(ctx, kb + ahalf * 48 + j * 8 + 4);
            uint2 p0 = pack4h(v0), p1 = pack4h(v1);
            asm volatile("st.shared.v4.b32 [%0], {%1, %2, %3, %4};"
                :: "r"(dA + j * 16), "r"(p0.x), "r"(p0.y), "r"(p1.x), "r"(p1.y));
        }
        CP_WAIT0();
        __syncthreads();
        mma_stage96(uA, uB, aoff, boff, acc);
    }
    MMA_EPI
}

// ---------------- LayerNorm (writes fp16) ------------------------------------
__device__ __forceinline__ float warp_sum(float v) {
    #pragma unroll
    for (int o = 16; o; o >>= 1) v += __shfl_xor_sync(0xffffffffu, v, o);
    return v;
}
__global__ void __launch_bounds__(128) ln_part_kernel(const float* __restrict__ src,
                                                      __half* __restrict__ dst,
                                                      const float* __restrict__ gg,
                                                      const float* __restrict__ be,
                                                      int shift) {
    int warp = threadIdx.x >> 5, lane = threadIdx.x & 31;
    int gidx = blockIdx.x * 4 + warp;
    int bw = gidx / 49, nn = gidx - bw * 49;
    int b = bw >> 8, wy = (bw >> 4) & 15, wx = bw & 15;
    int iy = nn / 7, ix = nn - iy * 7;
    int ys = wy * 7 + iy + shift; if (ys >= H2) ys -= H2;
    int xs = wx * 7 + ix + shift; if (xs >= H2) xs -= H2;
    const float* sp = src + ((size_t)b * LTOK + ys * H2 + xs) * C2;
    float v0 = sp[lane], v1 = sp[lane + 32], v2 = sp[lane + 64];
    float mean = warp_sum(v0 + v1 + v2) * (1.f / 96.f);
    float d0 = v0 - mean, d1 = v1 - mean, d2 = v2 - mean;
    float var = warp_sum(d0*d0 + d1*d1 + d2*d2) * (1.f / 96.f);
    float inv = rsqrtf(var + 1e-5f);
    __half* dp = dst + (size_t)gidx * C2;
    dp[lane]      = __float2half_rn(d0 * inv * gg[lane] + be[lane]);
    dp[lane + 32] = __float2half_rn(d1 * inv * gg[lane + 32] + be[lane + 32]);
    dp[lane + 64] = __float2half_rn(d2 * inv * gg[lane + 64] + be[lane + 64]);
}
__global__ void __launch_bounds__(128) ln_plain_kernel(const float* __restrict__ src,
                                                       __half* __restrict__ dst,
                                                       const float* __restrict__ gg,
                                                       const float* __restrict__ be) {
    int warp = threadIdx.x >> 5, lane = threadIdx.x & 31;
    size_t gidx = (size_t)blockIdx.x * 4 + warp;
    const float* sp = src + gidx * C2;
    float v0 = sp[lane], v1 = sp[lane + 32], v2 = sp[lane + 64];
    float mean = warp_sum(v0 + v1 + v2) * (1.f / 96.f);
    float d0 = v0 - mean, d1 = v1 - mean, d2 = v2 - mean;
    float var = warp_sum(d0*d0 + d1*d1 + d2*d2) * (1.f / 96.f);
    float inv = rsqrtf(var + 1e-5f);
    __half* dp = dst + gidx * C2;
    dp[lane]      = __float2half_rn(d0 * inv * gg[lane] + be[lane]);
    dp[lane + 32] = __float2half_rn(d1 * inv * gg[lane + 32] + be[lane + 32]);
    dp[lane + 64] = __float2half_rn(d2 * inv * gg[lane + 64] + be[lane + 64]);
}

// ---------------- window attention (writes fp16) -----------------------------
__global__ void __launch_bounds__(128) attn_kernel(const float* __restrict__ qkv,
                                                   const float* __restrict__ rel,
                                                   __half* __restrict__ outp,
                                                   int shifted) {
    __shared__ float sq[2*784], sk[2*784], sv[2*784], srel[2*169];
    __shared__ int slbl[49];
    const int bw = blockIdx.x, h0 = blockIdx.y * 2;
    const int tid = threadIdx.x;

    for (int i = tid; i < 2 * 784; i += 128) {
        int hh = i / 784, idx = i - hh * 784;
        int h = h0 + hh;
        sq[i] = qkv[(((size_t)(bw * 3 + 0) * 6 + h)) * 784 + idx];
        sk[i] = qkv[(((size_t)(bw * 3 + 1) * 6 + h)) * 784 + idx];
        sv[i] = qkv[(((size_t)(bw * 3 + 2) * 6 + h)) * 784 + idx];
    }
    for (int i = tid; i < 2 * 169; i += 128) {
        int hh = i / 169, idx = i - hh * 169;
        srel[i] = rel[idx * 6 + h0 + hh];
    }
    if (tid < 49) {
        if (shifted) {
            int wy = (bw >> 4) & 15, wx = bw & 15;
            int yy = wy * 7 + tid / 7, xx = wx * 7 + tid % 7;
            int ry = (yy < 105) ? 0 : ((yy < 109) ? 1 : 2);
            int rx = (xx < 105) ? 0 : ((xx < 109) ? 1 : 2);
            slbl[tid] = ry * 3 + rx;
        } else slbl[tid] = 0;
    }
    __syncthreads();

    const int h2 = tid >> 6, n = tid & 63;
    if (n < 49) {
        const float* qh = sq + h2 * 784;
        const float* kh = sk + h2 * 784;
        const float* vh = sv + h2 * 784;
        const float* rh = srel + h2 * 169;
        const int iy = n / 7, ix = n - iy * 7;
        float4 q0 = *(const float4*)&qh[n*16+0];
        float4 q1 = *(const float4*)&qh[n*16+4];
        float4 q2 = *(const float4*)&qh[n*16+8];
        float4 q3 = *(const float4*)&qh[n*16+12];
        const int mylbl = slbl[n];
        float s[49];
        float mx = -1e30f;
        #pragma unroll
        for (int m = 0; m < 49; m++) {
            int jy = m / 7, jx = m - jy * 7;
            float4 k0 = *(const float4*)&kh[m*16+0];
            float4 k1 = *(const float4*)&kh[m*16+4];
            float4 k2 = *(const float4*)&kh[m*16+8];
            float4 k3 = *(const float4*)&kh[m*16+12];
            float d = q0.x*k0.x+q0.y*k0.y+q0.z*k0.z+q0.w*k0.w
                    + q1.x*k1.x+q1.y*k1.y+q1.z*k1.z+q1.w*k1.w
                    + q2.x*k2.x+q2.y*k2.y+q2.z*k2.z+q2.w*k2.w
                    + q3.x*k3.x+q3.y*k3.y+q3.z*k3.z+q3.w*k3.w;
            d += rh[(iy - jy + 6) * 13 + (ix - jx + 6)];
            if (shifted && slbl[m] != mylbl) d -= 100.f;
            s[m] = d;
            mx = fmaxf(mx, d);
        }
        float sum = 0.f;
        #pragma unroll
        for (int m = 0; m < 49; m++) {
            float e = __expf(s[m] - mx);
            s[m] = e;
            sum += e;
        }
        float inv = 1.f / sum;
        float o[16];
        #pragma unroll
        for (int d = 0; d < 16; d++) o[d] = 0.f;
        #pragma unroll
        for (int m = 0; m < 49; m++) {
            float p = s[m] * inv;
            float4 v0 = *(const float4*)&vh[m*16+0];
            float4 v1 = *(const float4*)&vh[m*16+4];
            float4 v2 = *(const float4*)&vh[m*16+8];
            float4 v3 = *(const float4*)&vh[m*16+12];
            o[0]+=p*v0.x; o[1]+=p*v0.y; o[2]+=p*v0.z; o[3]+=p*v0.w;
            o[4]+=p*v1.x; o[5]+=p*v1.y; o[6]+=p*v1.z; o[7]+=p*v1.w;
            o[8]+=p*v2.x; o[9]+=p*v2.y; o[10]+=p*v2.z; o[11]+=p*v2.w;
            o[12]+=p*v3.x; o[13]+=p*v3.y; o[14]+=p*v3.z; o[15]+=p*v3.w;
        }
        uint32_t u[8];
        #pragma unroll
        for (int d = 0; d < 8; d++) u[d] = pack2h(o[2*d], o[2*d+1]);
        size_t o0 = ((size_t)bw * 49 + n) * C2 + (h0 + h2) * 16;
        ((uint4*)(outp + o0))[0] = make_uint4(u[0], u[1], u[2], u[3]);
        ((uint4*)(outp + o0))[1] = make_uint4(u[4], u[5], u[6], u[7]);
    }
}

// ---------------- launch -----------------------------------------------------
extern "C" void kernel_launch(void* const* d_in, const int* in_sizes, int n_in,
                              void* d_out, int out_size) {
    (void)in_sizes; (void)n_in; (void)out_size;
    const float* x     = (const float*)d_in[0];
    const float* up_w  = (const float*)d_in[1];
    const float* up_b  = (const float*)d_in[2];
    const float* bn_g  = (const float*)d_in[3];
    const float* bn_b  = (const float*)d_in[4];
    const float* bn_m  = (const float*)d_in[5];
    const float* bn_v  = (const float*)d_in[6];
    const float* n1g   = (const float*)d_in[7];
    const float* n1b   = (const float*)d_in[8];
    const float* qkvw  = (const float*)d_in[9];
    const float* qkvb  = (const float*)d_in[10];
    const float* projw = (const float*)d_in[11];
    const float* projb = (const float*)d_in[12];
    const float* rel   = (const float*)d_in[13];
    const float* n2g   = (const float*)d_in[14];
    const float* n2b   = (const float*)d_in[15];
    const float* f1w   = (const float*)d_in[16];
    const float* f1b   = (const float*)d_in[17];
    const float* f2w   = (const float*)d_in[18];
    const float* f2b   = (const float*)d_in[19];
    const float* outw  = (const float*)d_in[20];
    const float* outb  = (const float*)d_in[21];
    float* out = (float*)d_out;

    float *bX, *bQ, *scl, *sft;
    __half *bW, *bA, *bH, *wf;
    cudaGetSymbolAddress((void**)&bX, d_bufX);
    cudaGetSymbolAddress((void**)&bQ, d_bufQ);
    cudaGetSymbolAddress((void**)&bW, d_bW);
    cudaGetSymbolAddress((void**)&bA, d_bA);
    cudaGetSymbolAddress((void**)&bH, d_bH);
    cudaGetSymbolAddress((void**)&wf, d_wf);
    cudaGetSymbolAddress((void**)&scl, d_cscale);
    cudaGetSymbolAddress((void**)&sft, d_cshift);

    prep_conv<<<64, 256>>>(up_w, up_b, bn_g, bn_b, bn_m, bn_v);
    prep_w<<<221, 512>>>(qkvw, projw, f1w, f2w, outw);

    {   // fused 4-parity conv: blockIdx.z = parity
        ALConv al; al.in = x;
        StConv st; st.out = bX; st.scale = scl; st.shift = sft;
        mma_gemm_f<<<dim3(196, 1, 4), 256, SMEM_BYTES>>>(al, st, wf + OFF_WC, 96, 768, 96 * 768);
    }

    for (int i = 0; i < 2; i++) {
        int sh = i ? 3 : 0;
        ln_part_kernel<<<25088, 128>>>(bX, bW, n1g + i * 96, n1b + i * 96, sh);

        { StQKV st; st.out = bQ; st.bias = qkvb + i * 288;
          mma_gemm_p<<<dim3(784, 3), 256, SMEM_BYTES>>>(bW, st,
              wf + OFF_QKV + (size_t)i * 27648, 288, 96); }

        attn_kernel<<<dim3(2048, 3), 128>>>(bQ, rel + (size_t)i * 169 * 6, bA, sh);

        { StProj st; st.out = bX; st.bias = projb + i * 96; st.shift = sh;
          mma_gemm_p<<<dim3(784, 1), 256, SMEM_BYTES>>>(bA, st,
              wf + OFF_PROJ + (size_t)i * 9216, 96, 96); }

        ln_plain_kernel<<<25088, 128>>>(bX, bW, n2g + i * 96, n2b + i * 96);

        { StGelu st; st.outp = bH; st.bias = f1b + i * HID;
          mma_gemm_p<<<dim3(784, 4), 256, SMEM_BYTES>>>(bW, st,
              wf + OFF_F1 + (size_t)i * 36864, HID, 96); }

        { StFC2 st; st.out = bX; st.bias = f2b + i * 96;
          mma_gemm_p<<<dim3(784, 1), 256, SMEM_BYTES>>>(bH, st,
              wf + OFF_F2 + (size_t)i * 36864, 96, 384); }
    }

    { ALDirect al; al.A = bX; al.K = 96;
      StOut st; st.out = out; st.bias = outb;
      mma_gemm_f<<<dim3(784, 1, 1), 256, SMEM_BYTES>>>(al, st, wf + OFF_OUT, 48, 96, 0); }
}

// round 16
// speedup vs baseline: 2.5643x; 1.0220x over previous
#include <cuda_runtime.h>
#include <cuda_fp16.h>
#include <math.h>
#include <stdint.h>

#define CB 8
#define C2 96
#define H2 112
#define LTOK 12544
#define NWB 2048
#define HID 384

#define SROW 104
#define AS_H (128*SROW)
#define BS_H (96*SROW)
#define SMEM_BYTES ((AS_H + BS_H) * 2)          // staged kernels: 46592 B
#define SMEM_PS ((2*AS_H + BS_H) * 2)           // persistent: 73216 B

#define OFF_WC   0
#define OFF_QKV  294912
#define OFF_PROJ 350208
#define OFF_F1   368640
#define OFF_F2   442368
#define OFF_OUT  516096
#define TOTW     520704

__device__ float d_bufX[CB*LTOK*C2];
__device__ __half d_bufQ[NWB*3*6*49*16];
__device__ __half d_bW[CB*LTOK*C2];
__device__ __half d_bA[CB*LTOK*C2];
__device__ __half d_bH[CB*LTOK*HID];
__device__ __half d_wf[TOTW];
__device__ float d_cscale[96];
__device__ float d_cshift[96];

__device__ __forceinline__ uint32_t smem_u32(const void* p) {
    uint32_t a;
    asm("{ .reg .u64 t; cvta.to.shared.u64 t, %1; cvt.u32.u64 %0, t; }" : "=r"(a) : "l"(p));
    return a;
}
__device__ __forceinline__ void ldm_x4(uint32_t* r, uint32_t addr) {
    asm volatile("ldmatrix.sync.aligned.m8n8.x4.shared.b16 {%0,%1,%2,%3}, [%4];"
        : "=r"(r[0]), "=r"(r[1]), "=r"(r[2]), "=r"(r[3]) : "r"(addr));
}
__device__ __forceinline__ void ldm_x2(uint32_t* r, uint32_t addr) {
    asm volatile("ldmatrix.sync.aligned.m8n8.x2.shared.b16 {%0,%1}, [%2];"
        : "=r"(r[0]), "=r"(r[1]) : "r"(addr));
}
__device__ __forceinline__ void mma_f16(float* c, const uint32_t* a, const uint32_t* b) {
    asm volatile("mma.sync.aligned.m16n8k16.row.col.f32.f16.f16.f32 "
        "{%0,%1,%2,%3}, {%4,%5,%6,%7}, {%8,%9}, {%0,%1,%2,%3};"
        : "+f"(c[0]), "+f"(c[1]), "+f"(c[2]), "+f"(c[3])
        : "r"(a[0]), "r"(a[1]), "r"(a[2]), "r"(a[3]), "r"(b[0]), "r"(b[1]));
}
__device__ __forceinline__ void cpa16(uint32_t d, const void* g) {
    asm volatile("cp.async.ca.shared.global [%0], [%1], 16;" :: "r"(d), "l"(g) : "memory");
}
#define CP_COMMIT() asm volatile("cp.async.commit_group;" ::: "memory")
#define CP_WAIT1()  asm volatile("cp.async.wait_group 1;" ::: "memory")
#define CP_WAIT0()  asm volatile("cp.async.wait_group 0;" ::: "memory")

__device__ __forceinline__ uint32_t pack2h(float x, float y) {
    __half2 h = __floats2half2_rn(x, y);
    return *(uint32_t*)&h;
}
__device__ __forceinline__ uint2 pack4h(float4 v) {
    uint2 r;
    r.x = pack2h(v.x, v.y);
    r.y = pack2h(v.z, v.w);
    return r;
}

// ---------------- prep ----------------
__global__ void prep_conv(const float* __restrict__ up_w, const float* __restrict__ up_b,
                          const float* __restrict__ bn_g, const float* __restrict__ bn_b,
                          const float* __restrict__ bn_m, const float* __restrict__ bn_v) {
    int tid = blockIdx.x * blockDim.x + threadIdx.x;
    if (tid < 96) {
        float s = bn_g[tid] * rsqrtf(bn_v[tid] + 1e-5f);
        d_cscale[tid] = s;
        d_cshift[tid] = (up_b[tid] - bn_m[tid]) * s + bn_b[tid];
    }
    int total = 4 * 96 * 192;
    for (int idx = tid; idx < total; idx += gridDim.x * blockDim.x) {
        int p  = idx / (96 * 192);
        int r  = idx % (96 * 192);
        int co = r / 192, ci = r % 192;
        int py = p >> 1, px = p & 1;
        const float* w = up_w + ((size_t)co * 192 + ci) * 9;
        float cs[3][2];
        #pragma unroll
        for (int ky = 0; ky < 3; ky++) {
            float w0 = w[ky*3], w1 = w[ky*3+1], w2 = w[ky*3+2];
            cs[ky][0] = (px == 0) ? w0 : (w0 + w1);
            cs[ky][1] = (px == 0) ? (w1 + w2) : w2;
        }
        size_t dst = (size_t)OFF_WC + ((size_t)p * 96 + co) * 768 + ci * 4;
        float v[4];
        #pragma unroll
        for (int b2 = 0; b2 < 2; b2++) {
            v[b2]     = (py == 0) ? cs[0][b2] : (cs[0][b2] + cs[1][b2]);
            v[2 + b2] = (py == 0) ? (cs[1][b2] + cs[2][b2]) : cs[2][b2];
        }
        #pragma unroll
        for (int j = 0; j < 4; j++) d_wf[dst + j] = __float2half_rn(v[j]);
    }
}

__global__ void prep_w(const float* __restrict__ qkvw, const float* __restrict__ projw,
                       const float* __restrict__ f1w,  const float* __restrict__ f2w,
                       const float* __restrict__ outw) {
    int tid = blockIdx.x * blockDim.x + threadIdx.x;
    int total = TOTW - OFF_QKV;
    for (int idx = tid; idx < total; idx += gridDim.x * blockDim.x) {
        float v; size_t dst = OFF_QKV + idx;
        int r = idx;
        if (r < 55296)                 v = qkvw[r];
        else if ((r -= 55296) < 18432) v = projw[r];
        else if ((r -= 18432) < 73728) v = f1w[r];
        else if ((r -= 73728) < 73728) v = f2w[r];
        else                           v = outw[r - 73728];
        d_wf[dst] = __float2half_rn(v);
    }
}

// ---------------- float-A loaders ----------
struct ALDirect {
    const float* A; int K;
    struct Ctx { const float* p; };
    __device__ Ctx prep(int m) const { Ctx c; c.p = A + (size_t)m * K; return c; }
    __device__ float4 load(const Ctx& c, int k) const { return *(const float4*)(c.p + k); }
};
struct ALConv {
    const float* in;
    struct Ctx { const float* base; int o0, o1, o2, o3; };
    __device__ Ctx prep(int m) const {
        int py = blockIdx.z >> 1, px = blockIdx.z & 1;
        int b = m / 3136, r = m - b * 3136;
        int ty = r / 56, tx = r - ty * 56;
        int r0 = ty - 1 + py, r1 = r0 + 1;
        int c0 = tx - 1 + px, c1 = c0 + 1;
        bool r0v = (unsigned)r0 < 56u, r1v = (unsigned)r1 < 56u;
        bool c0v = (unsigned)c0 < 56u, c1v = (unsigned)c1 < 56u;
        Ctx c;
        c.base = in + (size_t)b * 192 * 3136;
        c.o0 = (r0v && c0v) ? r0 * 56 + c0 : -1;
        c.o1 = (r0v && c1v) ? r0 * 56 + c1 : -1;
        c.o2 = (r1v && c0v) ? r1 * 56 + c0 : -1;
        c.o3 = (r1v && c1v) ? r1 * 56 + c1 : -1;
        return c;
    }
    __device__ float4 load(const Ctx& c, int k) const {
        const float* p = c.base + (size_t)(k >> 2) * 3136;
        float4 v;
        v.x = (c.o0 >= 0) ? p[c.o0] : 0.f;
        v.y = (c.o1 >= 0) ? p[c.o1] : 0.f;
        v.z = (c.o2 >= 0) ? p[c.o2] : 0.f;
        v.w = (c.o3 >= 0) ? p[c.o3] : 0.f;
        return v;
    }
};

// ---------------- epilogues --------------------------------------------------
struct StConv {
    float* out; const float* scale; const float* shift;
    __device__ void store(int m, int n, float v) const {
        int py = blockIdx.z >> 1, px = blockIdx.z & 1;
        v = fmaxf(v * scale[n] + shift[n], 0.f);
        int b = m / 3136, r = m - b * 3136;
        int ty = r / 56, tx = r - ty * 56;
        int y = 2 * ty + py, x = 2 * tx + px;
        out[((size_t)b * LTOK + y * H2 + x) * C2 + n] = v;
    }
};
struct StQKV {
    __half* out; const float* bias;
    __device__ void store(int m, int n, float v) const {
        v += bias[n];
        int s3 = n / 96, rem = n - s3 * 96;
        int h = rem >> 4, d = rem & 15;
        if (s3 == 0) v *= 0.25f;
        int bw = m / 49, nn = m - bw * 49;
        out[(((size_t)(bw * 3 + s3) * 6 + h) * 49 + nn) * 16 + d] = __float2half_rn(v);
    }
};
struct StProj {
    float* out; const float* bias; int shift;
    __device__ void store(int m, int n, float v) const {
        int bw = m / 49, nn = m - bw * 49;
        int b = bw >> 8, wy = (bw >> 4) & 15, wx = bw & 15;
        int iy = nn / 7, ix = nn - iy * 7;
        int y = wy * 7 + iy + shift; if (y >= H2) y -= H2;
        int x = wx * 7 + ix + shift; if (x >= H2) x -= H2;
        out[((size_t)b * LTOK + y * H2 + x) * C2 + n] += v + bias[n];
    }
};
struct StGelu {
    __half* outp; const float* bias;
    __device__ void store(int m, int n, float v) const {
        v += bias[n];
        v = 0.5f * v * (1.0f + erff(v * 0.70710678118654752f));
        outp[(size_t)m * HID + n] = __float2half_rn(v);
    }
};
struct StFC2 {
    float* out; const float* bias;
    __device__ void store(int m, int n, float v) const {
        out[(size_t)m * C2 + n] += v + bias[n];
    }
};
struct StOut {
    float* out; const float* bias;
    __device__ void store(int m, int n, float v) const {
        v = fmaxf(v + bias[n], 0.f);
        int b = m / LTOK, pix = m - b * LTOK;
        out[((size_t)b * 48 + n) * LTOK + pix] = v;
    }
};

// ---------------- MMA stage --------------------------------------------------
__device__ __forceinline__ void mma_stage96(uint32_t uA, uint32_t uB,
                                            uint32_t aoff, uint32_t boff,
                                            float (&acc)[2][6][4]) {
    #pragma unroll
    for (int ks = 0; ks < 96; ks += 16) {
        uint32_t fA0[4], fA1[4];
        ldm_x4(fA0, uA + (aoff + ks) * 2);
        ldm_x4(fA1, uA + (aoff + 16 * SROW + ks) * 2);
        #pragma unroll
        for (int ni = 0; ni < 6; ni++) {
            uint32_t b[2];
            ldm_x2(b, uB + (boff + ni * 8 * SROW + ks) * 2);
            mma_f16(acc[0][ni], fA0, b);
            mma_f16(acc[1][ni], fA1, b);
        }
    }
}

#define MMA_WCOORD \
    const int tid = threadIdx.x; \
    const int wid = tid >> 5, lane = tid & 31; \
    const int wm = wid & 3, wn = wid >> 2; \
    const uint32_t aoff = (uint32_t)((wm * 32 + (lane & 15)) * SROW + (lane >> 4) * 8); \
    const uint32_t boff = (uint32_t)((wn * 48 + (lane & 7)) * SROW + ((lane >> 3) & 1) * 8);

#define ACC_ZERO \
    float acc[2][6][4]; \
    _Pragma("unroll") for (int mi2 = 0; mi2 < 2; mi2++) \
    _Pragma("unroll") for (int ni = 0; ni < 6; ni++) \
    _Pragma("unroll") for (int r = 0; r < 4; r++) acc[mi2][ni][r] = 0.f;

#define MMA_EPI(m0v) \
    _Pragma("unroll") for (int mi2 = 0; mi2 < 2; mi2++) \
    _Pragma("unroll") for (int ni = 0; ni < 6; ni++) \
    _Pragma("unroll") for (int r = 0; r < 4; r++) { \
        int m = (m0v) + wm * 32 + mi2 * 16 + (lane >> 2) + ((r >> 1) << 3); \
        int n = n0 + wn * 48 + ni * 8 + ((lane & 3) << 1) + (r & 1); \
        if (n < Nt) st.store(m, n, acc[mi2][ni][r]); \
    }

// ---------------- persistent GEMM: K=96, B resident, A ping-pong -------------
template<class ST>
__global__ void __launch_bounds__(256, 2) mma_gemm_ps(
        const __half* __restrict__ Ap, ST st, const __half* __restrict__ Bw,
        int Nt, int mblocks) {
    extern __shared__ uint16_t smx[];
    MMA_WCOORD
    const int n0 = blockIdx.y * 96;
    const uint32_t uA0 = smem_u32(smx);
    const uint32_t uA1 = uA0 + AS_H * 2;
    const uint32_t uB  = uA1 + AS_H * 2;

    // B once: 192 threads, 96 rows x 2 halves of 48
    if (tid < 192) {
        int brow = tid >> 1, bhalf = tid & 1;
        int brc = brow; if (n0 + brc >= Nt) brc = Nt - 1 - n0;
        const uint16_t* gB = (const uint16_t*)Bw + (size_t)(n0 + brc) * 96 + bhalf * 48;
        uint32_t dB = uB + (uint32_t)(brow * SROW + bhalf * 48) * 2;
        #pragma unroll
        for (int j = 0; j < 6; j++) cpa16(dB + j * 16, gB + j * 8);
    }
    CP_COMMIT();

    const int arow = tid & 127, ahalf = tid >> 7;
    const uint32_t dAoff = (uint32_t)(arow * SROW + ahalf * 48) * 2;

    int mi = blockIdx.x;
    if (mi < mblocks) {
        const uint16_t* gA = (const uint16_t*)Ap + ((size_t)(mi << 7) + arow) * 96 + ahalf * 48;
        #pragma unroll
        for (int j = 0; j < 6; j++) cpa16(uA0 + dAoff + j * 16, gA + j * 8);
    }
    CP_COMMIT();

    int li = 0;
    for (; mi < mblocks; mi += gridDim.x, li++) {
        const uint32_t ucur = (li & 1) ? uA1 : uA0;
        const uint32_t unxt = (li & 1) ? uA0 : uA1;
        const int mnext = mi + gridDim.x;
        if (mnext < mblocks) {
            const uint16_t* gA = (const uint16_t*)Ap + ((size_t)(mnext << 7) + arow) * 96 + ahalf * 48;
            #pragma unroll
            for (int j = 0; j < 6; j++) cpa16(unxt + dAoff + j * 16, gA + j * 8);
            CP_COMMIT();
            CP_WAIT1();
        } else {
            CP_WAIT0();
        }
        __syncthreads();
        ACC_ZERO
        mma_stage96(ucur, uB, aoff, boff, acc);
        MMA_EPI(mi << 7)
        __syncthreads();
    }
}

// ---------------- staged fp16-A GEMM (FC2: K=384) ----------------------------
template<class ST>
__global__ void __launch_bounds__(256, 2) mma_gemm_p(
        const __half* __restrict__ Ap, ST st, const __half* __restrict__ Bw,
        int Nt, int K) {
    extern __shared__ uint16_t smx[];
    MMA_WCOORD
    const int m0 = blockIdx.x << 7;
    const int n0 = blockIdx.y * 96;
    const uint32_t uA = smem_u32(smx);
    const uint32_t uB = uA + AS_H * 2;
    ACC_ZERO

    const int arow = tid & 127, ahalf = tid >> 7;
    const uint16_t* gA = (const uint16_t*)Ap + (size_t)(m0 + arow) * K + ahalf * 48;
    const uint32_t dA = uA + (uint32_t)(arow * SROW + ahalf * 48) * 2;
    const bool bact = tid < 192;
    const int brow = bact ? (tid >> 1) : 0;
    const int bhalf = tid & 1;
    int brc = brow; if (n0 + brc >= Nt) brc = Nt - 1 - n0;
    const uint16_t* gB = (const uint16_t*)Bw + (size_t)(n0 + brc) * K + bhalf * 48;
    const uint32_t dB = uB + (uint32_t)(brow * SROW + bhalf * 48) * 2;

    const int nst = K / 96;
    for (int kc = 0; kc < nst; kc++) {
        const int kb = kc * 96;
        if (kc > 0) __syncthreads();
        #pragma unroll
        for (int j = 0; j < 6; j++) cpa16(dA + j * 16, gA + kb + j * 8);
        if (bact) {
            #pragma unroll
            for (int j = 0; j < 6; j++) cpa16(dB + j * 16, gB + kb + j * 8);
        }
        CP_COMMIT();
        CP_WAIT0();
        __syncthreads();
        mma_stage96(uA, uB, aoff, boff, acc);
    }
    MMA_EPI(m0)
}

// ---------------- float-A GEMM (conv gather / out) ---------------------------
template<class AL, class ST>
__global__ void __launch_bounds__(256, 2) mma_gemm_f(
        AL al, ST st, const __half* __restrict__ Bw0,
        int Nt, int K, int wstride) {
    extern __shared__ uint16_t smx[];
    const __half* Bw = Bw0 + (size_t)blockIdx.z * wstride;
    MMA_WCOORD
    const int m0 = blockIdx.x << 7;
    const int n0 = blockIdx.y * 96;
    const uint32_t uA = smem_u32(smx);
    const uint32_t uB = uA + AS_H * 2;
    ACC_ZERO

    const int arow = tid & 127, ahalf = tid >> 7;
    typename AL::Ctx ctx = al.prep(m0 + arow);
    const uint32_t dA = uA + (uint32_t)(arow * SROW + ahalf * 48) * 2;
    const bool bact = tid < 192;
    const int brow = bact ? (tid >> 1) : 0;
    const int bhalf = tid & 1;
    int brc = brow; if (n0 + brc >= Nt) brc = Nt - 1 - n0;
    const uint16_t* gB = (const uint16_t*)Bw + (size_t)(n0 + brc) * K + bhalf * 48;
    const uint32_t dB = uB + (uint32_t)(brow * SROW + bhalf * 48) * 2;

    const int nst = K / 96;
    for (int kc = 0; kc < nst; kc++) {
        const int kb = kc * 96;
        if (kc > 0) __syncthreads();
        if (bact) {
            #pragma unroll
            for (int j = 0; j < 6; j++) cpa16(dB + j * 16, gB + kb + j * 8);
        }
        CP_COMMIT();
        #pragma unroll
        for (int j = 0; j < 6; j++) {
            float4 v0 = al.load(ctx, kb + ahalf * 48 + j * 8);
            float4 v1 = al.load(ctx, kb + ahalf * 48 + j * 8 + 4);
            uint2 p0 = pack4h(v0), p1 = pack4h(v1);
            asm volatile("st.shared.v4.b32 [%0], {%1, %2, %3, %4};"
                :: "r"(dA + j * 16), "r"(p0.x), "r"(p0.y), "r"(p1.x), "r"(p1.y));
        }
        CP_WAIT0();
        __syncthreads();
        mma_stage96(uA, uB, aoff, boff, acc);
    }
    MMA_EPI(m0)
}

// ---------------- LayerNorm --------------------------------------------------
__device__ __forceinline__ float warp_sum(float v) {
    #pragma unroll
    for (int o = 16; o; o >>= 1) v += __shfl_xor_sync(0xffffffffu, v, o);
    return v;
}
__global__ void __launch_bounds__(128) ln_part_kernel(const float* __restrict__ src,
                                                      __half* __restrict__ dst,
                                                      const float* __restrict__ gg,
                                                      const float* __restrict__ be,
                                                      int shift) {
    int warp = threadIdx.x >> 5, lane = threadIdx.x & 31;
    int gidx = blockIdx.x * 4 + warp;
    int bw = gidx / 49, nn = gidx - bw * 49;
    int b = bw >> 8, wy = (bw >> 4) & 15, wx = bw & 15;
    int iy = nn / 7, ix = nn - iy * 7;
    int ys = wy * 7 + iy + shift; if (ys >= H2) ys -= H2;
    int xs = wx * 7 + ix + shift; if (xs >= H2) xs -= H2;
    const float* sp = src + ((size_t)b * LTOK + ys * H2 + xs) * C2;
    float v0 = sp[lane], v1 = sp[lane + 32], v2 = sp[lane + 64];
    float mean = warp_sum(v0 + v1 + v2) * (1.f / 96.f);
    float d0 = v0 - mean, d1 = v1 - mean, d2 = v2 - mean;
    float var = warp_sum(d0*d0 + d1*d1 + d2*d2) * (1.f / 96.f);
    float inv = rsqrtf(var + 1e-5f);
    __half* dp = dst + (size_t)gidx * C2;
    dp[lane]      = __float2half_rn(d0 * inv * gg[lane] + be[lane]);
    dp[lane + 32] = __float2half_rn(d1 * inv * gg[lane + 32] + be[lane + 32]);
    dp[lane + 64] = __float2half_rn(d2 * inv * gg[lane + 64] + be[lane + 64]);
}
__global__ void __launch_bounds__(128) ln_plain_kernel(const float* __restrict__ src,
                                                       __half* __restrict__ dst,
                                                       const float* __restrict__ gg,
                                                       const float* __restrict__ be) {
    int warp = threadIdx.x >> 5, lane = threadIdx.x & 31;
    size_t gidx = (size_t)blockIdx.x * 4 + warp;
    const float* sp = src + gidx * C2;
    float v0 = sp[lane], v1 = sp[lane + 32], v2 = sp[lane + 64];
    float mean = warp_sum(v0 + v1 + v2) * (1.f / 96.f);
    float d0 = v0 - mean, d1 = v1 - mean, d2 = v2 - mean;
    float var = warp_sum(d0*d0 + d1*d1 + d2*d2) * (1.f / 96.f);
    float inv = rsqrtf(var + 1e-5f);
    __half* dp = dst + gidx * C2;
    dp[lane]      = __float2half_rn(d0 * inv * gg[lane] + be[lane]);
    dp[lane + 32] = __float2half_rn(d1 * inv * gg[lane + 32] + be[lane + 32]);
    dp[lane + 64] = __float2half_rn(d2 * inv * gg[lane + 64] + be[lane + 64]);
}

// ---------------- window attention (fp16 in, fp16 out) -----------------------
__global__ void __launch_bounds__(128) attn_kernel(const __half* __restrict__ qkv,
                                                   const float* __restrict__ rel,
                                                   __half* __restrict__ outp,
                                                   int shifted) {
    __shared__ float sq[2*784], sk[2*784], sv[2*784], srel[2*169];
    __shared__ int slbl[49];
    const int bw = blockIdx.x, h0 = blockIdx.y * 2;
    const int tid = threadIdx.x;

    for (int i = tid; i < 2 * 784; i += 128) {
        int hh = i / 784, idx = i - hh * 784;
        int h = h0 + hh;
        sq[i] = __half2float(qkv[(((size_t)(bw * 3 + 0) * 6 + h)) * 784 + idx]);
        sk[i] = __half2float(qkv[(((size_t)(bw * 3 + 1) * 6 + h)) * 784 + idx]);
        sv[i] = __half2float(qkv[(((size_t)(bw * 3 + 2) * 6 + h)) * 784 + idx]);
    }
    for (int i = tid; i < 2 * 169; i += 128) {
        int hh = i / 169, idx = i - hh * 169;
        srel[i] = rel[idx * 6 + h0 + hh];
    }
    if (tid < 49) {
        if (shifted) {
            int wy = (bw >> 4) & 15, wx = bw & 15;
            int yy = wy * 7 + tid / 7, xx = wx * 7 + tid % 7;
            int ry = (yy < 105) ? 0 : ((yy < 109) ? 1 : 2);
            int rx = (xx < 105) ? 0 : ((xx < 109) ? 1 : 2);
            slbl[tid] = ry * 3 + rx;
        } else slbl[tid] = 0;
    }
    __syncthreads();

    const int h2 = tid >> 6, n = tid & 63;
    if (n < 49) {
        const float* qh = sq + h2 * 784;
        const float* kh = sk + h2 * 784;
        const float* vh = sv + h2 * 784;
        const float* rh = srel + h2 * 169;
        const int iy = n / 7, ix = n - iy * 7;
        float4 q0 = *(const float4*)&qh[n*16+0];
        float4 q1 = *(const float4*)&qh[n*16+4];
        float4 q2 = *(const float4*)&qh[n*16+8];
        float4 q3 = *(const float4*)&qh[n*16+12];
        const int mylbl = slbl[n];
        float s[49];
        float mx = -1e30f;
        #pragma unroll
        for (int m = 0; m < 49; m++) {
            int jy = m / 7, jx = m - jy * 7;
            float4 k0 = *(const float4*)&kh[m*16+0];
            float4 k1 = *(const float4*)&kh[m*16+4];
            float4 k2 = *(const float4*)&kh[m*16+8];
            float4 k3 = *(const float4*)&kh[m*16+12];
            float d = q0.x*k0.x+q0.y*k0.y+q0.z*k0.z+q0.w*k0.w
                    + q1.x*k1.x+q1.y*k1.y+q1.z*k1.z+q1.w*k1.w
                    + q2.x*k2.x+q2.y*k2.y+q2.z*k2.z+q2.w*k2.w
                    + q3.x*k3.x+q3.y*k3.y+q3.z*k3.z+q3.w*k3.w;
            d += rh[(iy - jy + 6) * 13 + (ix - jx + 6)];
            if (shifted && slbl[m] != mylbl) d -= 100.f;
            s[m] = d;
            mx = fmaxf(mx, d);
        }
        float sum = 0.f;
        #pragma unroll
        for (int m = 0; m < 49; m++) {
            float e = __expf(s[m] - mx);
            s[m] = e;
            sum += e;
        }
        float inv = 1.f / sum;
        float o[16];
        #pragma unroll
        for (int d = 0; d < 16; d++) o[d] = 0.f;
        #pragma unroll
        for (int m = 0; m < 49; m++) {
            float p = s[m] * inv;
            float4 v0 = *(const float4*)&vh[m*16+0];
            float4 v1 = *(const float4*)&vh[m*16+4];
            float4 v2 = *(const float4*)&vh[m*16+8];
            float4 v3 = *(const float4*)&vh[m*16+12];
            o[0]+=p*v0.x; o[1]+=p*v0.y; o[2]+=p*v0.z; o[3]+=p*v0.w;
            o[4]+=p*v1.x; o[5]+=p*v1.y; o[6]+=p*v1.z; o[7]+=p*v1.w;
            o[8]+=p*v2.x; o[9]+=p*v2.y; o[10]+=p*v2.z; o[11]+=p*v2.w;
            o[12]+=p*v3.x; o[13]+=p*v3.y; o[14]+=p*v3.z; o[15]+=p*v3.w;
        }
        uint32_t u[8];
        #pragma unroll
        for (int d = 0; d < 8; d++) u[d] = pack2h(o[2*d], o[2*d+1]);
        size_t o0 = ((size_t)bw * 49 + n) * C2 + (h0 + h2) * 16;
        ((uint4*)(outp + o0))[0] = make_uint4(u[0], u[1], u[2], u[3]);
        ((uint4*)(outp + o0))[1] = make_uint4(u[4], u[5], u[6], u[7]);
    }
}

// ---------------- launch -----------------------------------------------------
extern "C" void kernel_launch(void* const* d_in, const int* in_sizes, int n_in,
                              void* d_out, int out_size) {
    (void)in_sizes; (void)n_in; (void)out_size;
    const float* x     = (const float*)d_in[0];
    const float* up_w  = (const float*)d_in[1];
    const float* up_b  = (const float*)d_in[2];
    const float* bn_g  = (const float*)d_in[3];
    const float* bn_b  = (const float*)d_in[4];
    const float* bn_m  = (const float*)d_in[5];
    const float* bn_v  = (const float*)d_in[6];
    const float* n1g   = (const float*)d_in[7];
    const float* n1b   = (const float*)d_in[8];
    const float* qkvw  = (const float*)d_in[9];
    const float* qkvb  = (const float*)d_in[10];
    const float* projw = (const float*)d_in[11];
    const float* projb = (const float*)d_in[12];
    const float* rel   = (const float*)d_in[13];
    const float* n2g   = (const float*)d_in[14];
    const float* n2b   = (const float*)d_in[15];
    const float* f1w   = (const float*)d_in[16];
    const float* f1b   = (const float*)d_in[17];
    const float* f2w   = (const float*)d_in[18];
    const float* f2b   = (const float*)d_in[19];
    const float* outw  = (const float*)d_in[20];
    const float* outb  = (const float*)d_in[21];
    float* out = (float*)d_out;

    float *bX, *scl, *sft;
    __half *bQ, *bW, *bA, *bH, *wf;
    cudaGetSymbolAddress((void**)&bX, d_bufX);
    cudaGetSymbolAddress((void**)&bQ, d_bufQ);
    cudaGetSymbolAddress((void**)&bW, d_bW);
    cudaGetSymbolAddress((void**)&bA, d_bA);
    cudaGetSymbolAddress((void**)&bH, d_bH);
    cudaGetSymbolAddress((void**)&wf, d_wf);
    cudaGetSymbolAddress((void**)&scl, d_cscale);
    cudaGetSymbolAddress((void**)&sft, d_cshift);

    cudaFuncSetAttribute(mma_gemm_ps<StQKV>,  cudaFuncAttributeMaxDynamicSharedMemorySize, SMEM_PS);
    cudaFuncSetAttribute(mma_gemm_ps<StProj>, cudaFuncAttributeMaxDynamicSharedMemorySize, SMEM_PS);
    cudaFuncSetAttribute(mma_gemm_ps<StGelu>, cudaFuncAttributeMaxDynamicSharedMemorySize, SMEM_PS);

    prep_conv<<<64, 256>>>(up_w, up_b, bn_g, bn_b, bn_m, bn_v);
    prep_w<<<221, 512>>>(qkvw, projw, f1w, f2w, outw);

    {   // fused 4-parity conv
        ALConv al; al.in = x;
        StConv st; st.out = bX; st.scale = scl; st.shift = sft;
        mma_gemm_f<<<dim3(196, 1, 4), 256, SMEM_BYTES>>>(al, st, wf + OFF_WC, 96, 768, 96 * 768);
    }

    for (int i = 0; i < 2; i++) {
        int sh = i ? 3 : 0;
        ln_part_kernel<<<25088, 128>>>(bX, bW, n1g + i * 96, n1b + i * 96, sh);

        { StQKV st; st.out = bQ; st.bias = qkvb + i * 288;
          mma_gemm_ps<<<dim3(98, 3), 256, SMEM_PS>>>(bW, st,
              wf + OFF_QKV + (size_t)i * 27648, 288, 784); }

        attn_kernel<<<dim3(2048, 3), 128>>>(bQ, rel + (size_t)i * 169 * 6, bA, sh);

        { StProj st; st.out = bX; st.bias = projb + i * 96; st.shift = sh;
          mma_gemm_ps<<<dim3(296, 1), 256, SMEM_PS>>>(bA, st,
              wf + OFF_PROJ + (size_t)i * 9216, 96, 784); }

        ln_plain_kernel<<<25088, 128>>>(bX, bW, n2g + i * 96, n2b + i * 96);

        { StGelu st; st.outp = bH; st.bias = f1b + i * HID;
          mma_gemm_ps<<<dim3(74, 4), 256, SMEM_PS>>>(bW, st,
              wf + OFF_F1 + (size_t)i * 36864, HID, 784); }

        { StFC2 st; st.out = bX; st.bias = f2b + i * 96;
          mma_gemm_p<<<dim3(784, 1), 256, SMEM_BYTES>>>(bH, st,
              wf + OFF_F2 + (size_t)i * 36864, 96, 384); }
    }

    { ALDirect al; al.A = bX; al.K = 96;
      StOut st; st.out = out; st.bias = outb;
      mma_gemm_f<<<dim3(784, 1, 1), 256, SMEM_BYTES>>>(al, st, wf + OFF_OUT, 48, 96, 0); }
}

// round 17
// speedup vs baseline: 2.6502x; 1.0335x over previous
#include <cuda_runtime.h>
#include <cuda_fp16.h>
#include <math.h>
#include <stdint.h>

#define CB 8
#define C2 96
#define H2 112
#define LTOK 12544
#define NWB 2048
#define HID 384

#define SROW 104
#define AS_H (128*SROW)
#define BS_H (96*SROW)
#define SMEM_BYTES ((AS_H + BS_H) * 2)     // plain staged: 46592 B
#define SMEM_F 49664                        // fused-LN staged: 128*97*4 B
#define SMEM_PS ((2*AS_H + BS_H) * 2)      // persistent: 73216 B

#define OFF_WC   0
#define OFF_QKV  294912
#define OFF_PROJ 350208
#define OFF_F1   368640
#define OFF_F2   442368
#define OFF_OUT  516096
#define TOTW     520704

__device__ float d_bufX[CB*LTOK*C2];
__device__ __half d_bufQ[NWB*3*6*49*16];
__device__ __half d_bW[CB*LTOK*C2];
__device__ __half d_bA[CB*LTOK*C2];
__device__ __half d_bH[CB*LTOK*HID];
__device__ __half d_wf[TOTW];
__device__ float d_cscale[96];
__device__ float d_cshift[96];

__device__ __forceinline__ uint32_t smem_u32(const void* p) {
    uint32_t a;
    asm("{ .reg .u64 t; cvta.to.shared.u64 t, %1; cvt.u32.u64 %0, t; }" : "=r"(a) : "l"(p));
    return a;
}
__device__ __forceinline__ void ldm_x4(uint32_t* r, uint32_t addr) {
    asm volatile("ldmatrix.sync.aligned.m8n8.x4.shared.b16 {%0,%1,%2,%3}, [%4];"
        : "=r"(r[0]), "=r"(r[1]), "=r"(r[2]), "=r"(r[3]) : "r"(addr));
}
__device__ __forceinline__ void ldm_x2(uint32_t* r, uint32_t addr) {
    asm volatile("ldmatrix.sync.aligned.m8n8.x2.shared.b16 {%0,%1}, [%2];"
        : "=r"(r[0]), "=r"(r[1]) : "r"(addr));
}
__device__ __forceinline__ void mma_f16(float* c, const uint32_t* a, const uint32_t* b) {
    asm volatile("mma.sync.aligned.m16n8k16.row.col.f32.f16.f16.f32 "
        "{%0,%1,%2,%3}, {%4,%5,%6,%7}, {%8,%9}, {%0,%1,%2,%3};"
        : "+f"(c[0]), "+f"(c[1]), "+f"(c[2]), "+f"(c[3])
        : "r"(a[0]), "r"(a[1]), "r"(a[2]), "r"(a[3]), "r"(b[0]), "r"(b[1]));
}
__device__ __forceinline__ void cpa16(uint32_t d, const void* g) {
    asm volatile("cp.async.ca.shared.global [%0], [%1], 16;" :: "r"(d), "l"(g) : "memory");
}
#define CP_COMMIT() asm volatile("cp.async.commit_group;" ::: "memory")
#define CP_WAIT1()  asm volatile("cp.async.wait_group 1;" ::: "memory")
#define CP_WAIT0()  asm volatile("cp.async.wait_group 0;" ::: "memory")

__device__ __forceinline__ uint32_t pack2h(float x, float y) {
    __half2 h = __floats2half2_rn(x, y);
    return *(uint32_t*)&h;
}
__device__ __forceinline__ uint2 pack4h(float4 v) {
    uint2 r;
    r.x = pack2h(v.x, v.y);
    r.y = pack2h(v.z, v.w);
    return r;
}
__device__ __forceinline__ float warp_sum(float v) {
    #pragma unroll
    for (int o = 16; o; o >>= 1) v += __shfl_xor_sync(0xffffffffu, v, o);
    return v;
}

// ---------------- prep ----------------
__global__ void prep_conv(const float* __restrict__ up_w, const float* __restrict__ up_b,
                          const float* __restrict__ bn_g, const float* __restrict__ bn_b,
                          const float* __restrict__ bn_m, const float* __restrict__ bn_v) {
    int tid = blockIdx.x * blockDim.x + threadIdx.x;
    if (tid < 96) {
        float s = bn_g[tid] * rsqrtf(bn_v[tid] + 1e-5f);
        d_cscale[tid] = s;
        d_cshift[tid] = (up_b[tid] - bn_m[tid]) * s + bn_b[tid];
    }
    int total = 4 * 96 * 192;
    for (int idx = tid; idx < total; idx += gridDim.x * blockDim.x) {
        int p  = idx / (96 * 192);
        int r  = idx % (96 * 192);
        int co = r / 192, ci = r % 192;
        int py = p >> 1, px = p & 1;
        const float* w = up_w + ((size_t)co * 192 + ci) * 9;
        float cs[3][2];
        #pragma unroll
        for (int ky = 0; ky < 3; ky++) {
            float w0 = w[ky*3], w1 = w[ky*3+1], w2 = w[ky*3+2];
            cs[ky][0] = (px == 0) ? w0 : (w0 + w1);
            cs[ky][1] = (px == 0) ? (w1 + w2) : w2;
        }
        size_t dst = (size_t)OFF_WC + ((size_t)p * 96 + co) * 768 + ci * 4;
        float v[4];
        #pragma unroll
        for (int b2 = 0; b2 < 2; b2++) {
            v[b2]     = (py == 0) ? cs[0][b2] : (cs[0][b2] + cs[1][b2]);
            v[2 + b2] = (py == 0) ? (cs[1][b2] + cs[2][b2]) : cs[2][b2];
        }
        #pragma unroll
        for (int j = 0; j < 4; j++) d_wf[dst + j] = __float2half_rn(v[j]);
    }
}

__global__ void prep_w(const float* __restrict__ qkvw, const float* __restrict__ projw,
                       const float* __restrict__ f1w,  const float* __restrict__ f2w,
                       const float* __restrict__ outw) {
    int tid = blockIdx.x * blockDim.x + threadIdx.x;
    int total = TOTW - OFF_QKV;
    for (int idx = tid; idx < total; idx += gridDim.x * blockDim.x) {
        float v; size_t dst = OFF_QKV + idx;
        int r = idx;
        if (r < 55296)                 v = qkvw[r];
        else if ((r -= 55296) < 18432) v = projw[r];
        else if ((r -= 18432) < 73728) v = f1w[r];
        else if ((r -= 73728) < 73728) v = f2w[r];
        else                           v = outw[r - 73728];
        d_wf[dst] = __float2half_rn(v);
    }
}

// ---------------- loaders ----------
struct ALDirect {
    const float* A; int K;
    struct Ctx { const float* p; };
    __device__ Ctx prep(int m) const { Ctx c; c.p = A + (size_t)m * K; return c; }
    __device__ float4 load(const Ctx& c, int k) const { return *(const float4*)(c.p + k); }
};
struct ALConv {
    const float* in;
    struct Ctx { const float* base; int o0, o1, o2, o3; };
    __device__ Ctx prep(int m) const {
        int py = blockIdx.z >> 1, px = blockIdx.z & 1;
        int b = m / 3136, r = m - b * 3136;
        int ty = r / 56, tx = r - ty * 56;
        int r0 = ty - 1 + py, r1 = r0 + 1;
        int c0 = tx - 1 + px, c1 = c0 + 1;
        bool r0v = (unsigned)r0 < 56u, r1v = (unsigned)r1 < 56u;
        bool c0v = (unsigned)c0 < 56u, c1v = (unsigned)c1 < 56u;
        Ctx c;
        c.base = in + (size_t)b * 192 * 3136;
        c.o0 = (r0v && c0v) ? r0 * 56 + c0 : -1;
        c.o1 = (r0v && c1v) ? r0 * 56 + c1 : -1;
        c.o2 = (r1v && c0v) ? r1 * 56 + c0 : -1;
        c.o3 = (r1v && c1v) ? r1 * 56 + c1 : -1;
        return c;
    }
    __device__ float4 load(const Ctx& c, int k) const {
        const float* p = c.base + (size_t)(k >> 2) * 3136;
        float4 v;
        v.x = (c.o0 >= 0) ? p[c.o0] : 0.f;
        v.y = (c.o1 >= 0) ? p[c.o1] : 0.f;
        v.z = (c.o2 >= 0) ? p[c.o2] : 0.f;
        v.w = (c.o3 >= 0) ? p[c.o3] : 0.f;
        return v;
    }
};

// ---------------- epilogues (non-fused) --------------------------------------
struct StQKV {
    __half* out; const float* bias;
    __device__ void store(int m, int n, float v) const {
        v += bias[n];
        int s3 = n / 96, rem = n - s3 * 96;
        int h = rem >> 4, d = rem & 15;
        if (s3 == 0) v *= 0.25f;
        int bw = m / 49, nn = m - bw * 49;
        out[(((size_t)(bw * 3 + s3) * 6 + h) * 49 + nn) * 16 + d] = __float2half_rn(v);
    }
};
struct StGelu {
    __half* outp; const float* bias;
    __device__ void store(int m, int n, float v) const {
        v += bias[n];
        v = 0.5f * v * (1.0f + erff(v * 0.70710678118654752f));
        outp[(size_t)m * HID + n] = __float2half_rn(v);
    }
};
struct StFC2 {
    float* out; const float* bias;
    __device__ void store(int m, int n, float v) const {
        out[(size_t)m * C2 + n] += v + bias[n];
    }
};
struct StOut {
    float* out; const float* bias;
    __device__ void store(int m, int n, float v) const {
        v = fmaxf(v + bias[n], 0.f);
        int b = m / LTOK, pix = m - b * LTOK;
        out[((size_t)b * 48 + n) * LTOK + pix] = v;
    }
};

// ---------------- MMA stage --------------------------------------------------
__device__ __forceinline__ void mma_stage96(uint32_t uA, uint32_t uB,
                                            uint32_t aoff, uint32_t boff,
                                            float (&acc)[2][6][4]) {
    #pragma unroll
    for (int ks = 0; ks < 96; ks += 16) {
        uint32_t fA0[4], fA1[4];
        ldm_x4(fA0, uA + (aoff + ks) * 2);
        ldm_x4(fA1, uA + (aoff + 16 * SROW + ks) * 2);
        #pragma unroll
        for (int ni = 0; ni < 6; ni++) {
            uint32_t b[2];
            ldm_x2(b, uB + (boff + ni * 8 * SROW + ks) * 2);
            mma_f16(acc[0][ni], fA0, b);
            mma_f16(acc[1][ni], fA1, b);
        }
    }
}

#define MMA_WCOORD \
    const int tid = threadIdx.x; \
    const int wid = tid >> 5, lane = tid & 31; \
    const int wm = wid & 3, wn = wid >> 2; \
    const uint32_t aoff = (uint32_t)((wm * 32 + (lane & 15)) * SROW + (lane >> 4) * 8); \
    const uint32_t boff = (uint32_t)((wn * 48 + (lane & 7)) * SROW + ((lane >> 3) & 1) * 8);

#define ACC_ZERO \
    float acc[2][6][4]; \
    _Pragma("unroll") for (int mi2 = 0; mi2 < 2; mi2++) \
    _Pragma("unroll") for (int ni = 0; ni < 6; ni++) \
    _Pragma("unroll") for (int r = 0; r < 4; r++) acc[mi2][ni][r] = 0.f;

#define MMA_EPI(m0v) \
    _Pragma("unroll") for (int mi2 = 0; mi2 < 2; mi2++) \
    _Pragma("unroll") for (int ni = 0; ni < 6; ni++) \
    _Pragma("unroll") for (int r = 0; r < 4; r++) { \
        int m = (m0v) + wm * 32 + mi2 * 16 + (lane >> 2) + ((r >> 1) << 3); \
        int n = n0 + wn * 48 + ni * 8 + ((lane & 3) << 1) + (r & 1); \
        if (n < Nt) st.store(m, n, acc[mi2][ni][r]); \
    }

// fused-LN helper: stage(rowlocal, n, value); then LN pass per warp
__device__ __forceinline__ void ln_rows(float* stg, int wid, int lane,
                                        const float* lng, const float* lnb,
                                        __half* const* dsts) {
    #pragma unroll 1
    for (int rr = wid * 16; rr < wid * 16 + 16; rr++) {
        const float* row = stg + rr * 97;
        float v0 = row[lane], v1 = row[lane + 32], v2 = row[lane + 64];
        float mean = warp_sum(v0 + v1 + v2) * (1.f / 96.f);
        float dd0 = v0 - mean, dd1 = v1 - mean, dd2 = v2 - mean;
        float var = warp_sum(dd0*dd0 + dd1*dd1 + dd2*dd2) * (1.f / 96.f);
        float inv = rsqrtf(var + 1e-5f);
        __half* dp = dsts[rr & 15];
        dp[lane]      = __float2half_rn(dd0 * inv * lng[lane] + lnb[lane]);
        dp[lane + 32] = __float2half_rn(dd1 * inv * lng[lane + 32] + lnb[lane + 32]);
        dp[lane + 64] = __float2half_rn(dd2 * inv * lng[lane + 64] + lnb[lane + 64]);
    }
}

// ---------------- persistent GEMM: K=96, B resident, A ping-pong -------------
template<class ST>
__global__ void __launch_bounds__(256, 2) mma_gemm_ps(
        const __half* __restrict__ Ap, ST st, const __half* __restrict__ Bw,
        int Nt, int mblocks) {
    extern __shared__ uint16_t smx[];
    MMA_WCOORD
    const int n0 = blockIdx.y * 96;
    const uint32_t uA0 = smem_u32(smx);
    const uint32_t uA1 = uA0 + AS_H * 2;
    const uint32_t uB  = uA1 + AS_H * 2;

    if (tid < 192) {
        int brow = tid >> 1, bhalf = tid & 1;
        int brc = brow; if (n0 + brc >= Nt) brc = Nt - 1 - n0;
        const uint16_t* gB = (const uint16_t*)Bw + (size_t)(n0 + brc) * 96 + bhalf * 48;
        uint32_t dB = uB + (uint32_t)(brow * SROW + bhalf * 48) * 2;
        #pragma unroll
        for (int j = 0; j < 6; j++) cpa16(dB + j * 16, gB + j * 8);
    }
    CP_COMMIT();

    const int arow = tid & 127, ahalf = tid >> 7;
    const uint32_t dAoff = (uint32_t)(arow * SROW + ahalf * 48) * 2;

    int mi = blockIdx.x;
    if (mi < mblocks) {
        const uint16_t* gA = (const uint16_t*)Ap + ((size_t)(mi << 7) + arow) * 96 + ahalf * 48;
        #pragma unroll
        for (int j = 0; j < 6; j++) cpa16(uA0 + dAoff + j * 16, gA + j * 8);
    }
    CP_COMMIT();

    int li = 0;
    for (; mi < mblocks; mi += gridDim.x, li++) {
        const uint32_t ucur = (li & 1) ? uA1 : uA0;
        const uint32_t unxt = (li & 1) ? uA0 : uA1;
        const int mnext = mi + gridDim.x;
        if (mnext < mblocks) {
            const uint16_t* gA = (const uint16_t*)Ap + ((size_t)(mnext << 7) + arow) * 96 + ahalf * 48;
            #pragma unroll
            for (int j = 0; j < 6; j++) cpa16(unxt + dAoff + j * 16, gA + j * 8);
            CP_COMMIT();
            CP_WAIT1();
        } else {
            CP_WAIT0();
        }
        __syncthreads();
        ACC_ZERO
        mma_stage96(ucur, uB, aoff, boff, acc);
        MMA_EPI(mi << 7)
        __syncthreads();
    }
}

// ---------------- staged fp16-A GEMM (plain epilogue) ------------------------
template<class ST>
__global__ void __launch_bounds__(256, 2) mma_gemm_p(
        const __half* __restrict__ Ap, ST st, const __half* __restrict__ Bw,
        int Nt, int K) {
    extern __shared__ uint16_t smx[];
    MMA_WCOORD
    const int m0 = blockIdx.x << 7;
    const int n0 = blockIdx.y * 96;
    const uint32_t uA = smem_u32(smx);
    const uint32_t uB = uA + AS_H * 2;
    ACC_ZERO

    const int arow = tid & 127, ahalf = tid >> 7;
    const uint16_t* gA = (const uint16_t*)Ap + (size_t)(m0 + arow) * K + ahalf * 48;
    const uint32_t dA = uA + (uint32_t)(arow * SROW + ahalf * 48) * 2;
    const bool bact = tid < 192;
    const int brow = bact ? (tid >> 1) : 0;
    const int bhalf = tid & 1;
    int brc = brow; if (n0 + brc >= Nt) brc = Nt - 1 - n0;
    const uint16_t* gB = (const uint16_t*)Bw + (size_t)(n0 + brc) * K + bhalf * 48;
    const uint32_t dB = uB + (uint32_t)(brow * SROW + bhalf * 48) * 2;

    const int nst = K / 96;
    for (int kc = 0; kc < nst; kc++) {
        const int kb = kc * 96;
        if (kc > 0) __syncthreads();
        #pragma unroll
        for (int j = 0; j < 6; j++) cpa16(dA + j * 16, gA + kb + j * 8);
        if (bact) {
            #pragma unroll
            for (int j = 0; j < 6; j++) cpa16(dB + j * 16, gB + kb + j * 8);
        }
        CP_COMMIT();
        CP_WAIT0();
        __syncthreads();
        mma_stage96(uA, uB, aoff, boff, acc);
    }
    MMA_EPI(m0)
}

// ---------------- staged fp16-A GEMM + residual + fused LN -------------------
// MODE 0: proj  (window-token rows; RMW bX at shifted y,x; LN2 -> bW at linear)
// MODE 1: fc2   (linear rows; RMW bX at m; LN1 shift -> bW at windowed gidx)
template<int MODE>
__global__ void __launch_bounds__(256, 2) mma_gemm_pf(
        const __half* __restrict__ Ap, const __half* __restrict__ Bw, int K,
        float* __restrict__ bX, __half* __restrict__ bWp,
        const float* __restrict__ bias,
        const float* __restrict__ lng, const float* __restrict__ lnb, int shift) {
    extern __shared__ uint16_t smx[];
    MMA_WCOORD
    const int m0 = blockIdx.x << 7;
    const uint32_t uA = smem_u32(smx);
    const uint32_t uB = uA + AS_H * 2;
    ACC_ZERO

    const int arow = tid & 127, ahalf = tid >> 7;
    const uint16_t* gA = (const uint16_t*)Ap + (size_t)(m0 + arow) * K + ahalf * 48;
    const uint32_t dA = uA + (uint32_t)(arow * SROW + ahalf * 48) * 2;
    const bool bact = tid < 192;
    const int brow = bact ? (tid >> 1) : 0;
    const int bhalf = tid & 1;
    const uint16_t* gB = (const uint16_t*)Bw + (size_t)brow * K + bhalf * 48;
    const uint32_t dB = uB + (uint32_t)(brow * SROW + bhalf * 48) * 2;

    const int nst = K / 96;
    for (int kc = 0; kc < nst; kc++) {
        const int kb = kc * 96;
        if (kc > 0) __syncthreads();
        #pragma unroll
        for (int j = 0; j < 6; j++) cpa16(dA + j * 16, gA + kb + j * 8);
        if (bact) {
            #pragma unroll
            for (int j = 0; j < 6; j++) cpa16(dB + j * 16, gB + kb + j * 8);
        }
        CP_COMMIT();
        CP_WAIT0();
        __syncthreads();
        mma_stage96(uA, uB, aoff, boff, acc);
    }

    __syncthreads();                      // tiles dead; reuse as fp32 stage
    float* stg = (float*)smx;
    #pragma unroll
    for (int mi2 = 0; mi2 < 2; mi2++)
    #pragma unroll
    for (int ni = 0; ni < 6; ni++)
    #pragma unroll
    for (int r = 0; r < 4; r++) {
        int rl = wm * 32 + mi2 * 16 + (lane >> 2) + ((r >> 1) << 3);
        int m  = m0 + rl;
        int n  = wn * 48 + ni * 8 + ((lane & 3) << 1) + (r & 1);
        size_t idx;
        if (MODE == 0) {
            int bw = m / 49, nn = m - bw * 49;
            int b = bw >> 8, wy = (bw >> 4) & 15, wx = bw & 15;
            int iy = nn / 7, ix = nn - iy * 7;
            int y = wy * 7 + iy + shift; if (y >= H2) y -= H2;
            int x = wx * 7 + ix + shift; if (x >= H2) x -= H2;
            idx = ((size_t)b * LTOK + y * H2 + x) * C2 + n;
        } else {
            idx = (size_t)m * C2 + n;
        }
        float vb = bX[idx] + acc[mi2][ni][r] + bias[n];
        bX[idx] = vb;
        stg[rl * 97 + n] = vb;
    }
    __syncthreads();

    __half* dsts[16];
    #pragma unroll 1
    for (int rr = wid * 16; rr < wid * 16 + 16; rr++) {
        int m = m0 + rr;
        size_t o;
        if (MODE == 0) {
            int bw = m / 49, nn = m - bw * 49;
            int b = bw >> 8, wy = (bw >> 4) & 15, wx = bw & 15;
            int iy = nn / 7, ix = nn - iy * 7;
            int y = wy * 7 + iy + shift; if (y >= H2) y -= H2;
            int x = wx * 7 + ix + shift; if (x >= H2) x -= H2;
            o = ((size_t)b * LTOK + y * H2 + x) * C2;
        } else {
            int b = m / LTOK, r2 = m - b * LTOK;
            int y = r2 / H2, x = r2 - y * H2;
            int yy = y - shift; if (yy < 0) yy += H2;
            int xx = x - shift; if (xx < 0) xx += H2;
            int bw = b * 256 + (yy / 7) * 16 + (xx / 7);
            o = ((size_t)bw * 49 + (yy % 7) * 7 + (xx % 7)) * C2;
        }
        dsts[rr & 15] = bWp + o;
        const float* row = stg + rr * 97;
        float v0 = row[lane], v1 = row[lane + 32], v2 = row[lane + 64];
        float mean = warp_sum(v0 + v1 + v2) * (1.f / 96.f);
        float dd0 = v0 - mean, dd1 = v1 - mean, dd2 = v2 - mean;
        float var = warp_sum(dd0*dd0 + dd1*dd1 + dd2*dd2) * (1.f / 96.f);
        float inv = rsqrtf(var + 1e-5f);
        __half* dp = dsts[rr & 15];
        dp[lane]      = __float2half_rn(dd0 * inv * lng[lane] + lnb[lane]);
        dp[lane + 32] = __float2half_rn(dd1 * inv * lng[lane + 32] + lnb[lane + 32]);
        dp[lane + 64] = __float2half_rn(dd2 * inv * lng[lane + 64] + lnb[lane + 64]);
    }
}

// ---------------- conv GEMM + BN/ReLU + fused LN1(shift0) --------------------
__global__ void __launch_bounds__(256, 2) conv_ln_kernel(
        ALConv al, const __half* __restrict__ Bw0, int wstride,
        float* __restrict__ bX, __half* __restrict__ bWp,
        const float* __restrict__ scale, const float* __restrict__ cshift,
        const float* __restrict__ lng, const float* __restrict__ lnb) {
    extern __shared__ uint16_t smx[];
    const __half* Bw = (const __half*)Bw0 + (size_t)blockIdx.z * wstride;
    MMA_WCOORD
    const int m0 = blockIdx.x << 7;
    const uint32_t uA = smem_u32(smx);
    const uint32_t uB = uA + AS_H * 2;
    ACC_ZERO
    const int K = 768;

    const int arow = tid & 127, ahalf = tid >> 7;
    typename ALConv::Ctx ctx = al.prep(m0 + arow);
    const uint32_t dA = uA + (uint32_t)(arow * SROW + ahalf * 48) * 2;
    const bool bact = tid < 192;
    const int brow = bact ? (tid >> 1) : 0;
    const int bhalf = tid & 1;
    const uint16_t* gB = (const uint16_t*)Bw + (size_t)brow * K + bhalf * 48;
    const uint32_t dB = uB + (uint32_t)(brow * SROW + bhalf * 48) * 2;

    const int nst = K / 96;
    for (int kc = 0; kc < nst; kc++) {
        const int kb = kc * 96;
        if (kc > 0) __syncthreads();
        if (bact) {
            #pragma unroll
            for (int j = 0; j < 6; j++) cpa16(dB + j * 16, gB + kb + j * 8);
        }
        CP_COMMIT();
        #pragma unroll
        for (int j = 0; j < 6; j++) {
            float4 v0 = al.load(ctx, kb + ahalf * 48 + j * 8);
            float4 v1 = al.load(ctx, kb + ahalf * 48 + j * 8 + 4);
            uint2 p0 = pack4h(v0), p1 = pack4h(v1);
            asm volatile("st.shared.v4.b32 [%0], {%1, %2, %3, %4};"
                :: "r"(dA + j * 16), "r"(p0.x), "r"(p0.y), "r"(p1.x), "r"(p1.y));
        }
        CP_WAIT0();
        __syncthreads();
        mma_stage96(uA, uB, aoff, boff, acc);
    }

    const int py = blockIdx.z >> 1, px = blockIdx.z & 1;
    __syncthreads();
    float* stg = (float*)smx;
    #pragma unroll
    for (int mi2 = 0; mi2 < 2; mi2++)
    #pragma unroll
    for (int ni = 0; ni < 6; ni++)
    #pragma unroll
    for (int r = 0; r < 4; r++) {
        int rl = wm * 32 + mi2 * 16 + (lane >> 2) + ((r >> 1) << 3);
        int m  = m0 + rl;
        int n  = wn * 48 + ni * 8 + ((lane & 3) << 1) + (r & 1);
        float v = fmaxf(acc[mi2][ni][r] * scale[n] + cshift[n], 0.f);
        int b = m / 3136, rr2 = m - b * 3136;
        int ty = rr2 / 56, tx = rr2 - ty * 56;
        int y = 2 * ty + py, x = 2 * tx + px;
        bX[((size_t)b * LTOK + y * H2 + x) * C2 + n] = v;
        stg[rl * 97 + n] = v;
    }
    __syncthreads();

    #pragma unroll 1
    for (int rr = wid * 16; rr < wid * 16 + 16; rr++) {
        int m = m0 + rr;
        int b = m / 3136, rr2 = m - b * 3136;
        int ty = rr2 / 56, tx = rr2 - ty * 56;
        int y = 2 * ty + py, x = 2 * tx + px;
        int bw = b * 256 + (y / 7) * 16 + (x / 7);
        __half* dp = bWp + ((size_t)bw * 49 + (y % 7) * 7 + (x % 7)) * C2;
        const float* row = stg + rr * 97;
        float v0 = row[lane], v1 = row[lane + 32], v2 = row[lane + 64];
        float mean = warp_sum(v0 + v1 + v2) * (1.f / 96.f);
        float dd0 = v0 - mean, dd1 = v1 - mean, dd2 = v2 - mean;
        float var = warp_sum(dd0*dd0 + dd1*dd1 + dd2*dd2) * (1.f / 96.f);
        float inv = rsqrtf(var + 1e-5f);
        dp[lane]      = __float2half_rn(dd0 * inv * lng[lane] + lnb[lane]);
        dp[lane + 32] = __float2half_rn(dd1 * inv * lng[lane + 32] + lnb[lane + 32]);
        dp[lane + 64] = __float2half_rn(dd2 * inv * lng[lane + 64] + lnb[lane + 64]);
    }
}

// ---------------- float-A GEMM (out conv) ------------------------------------
template<class AL, class ST>
__global__ void __launch_bounds__(256, 2) mma_gemm_f(
        AL al, ST st, const __half* __restrict__ Bw,
        int Nt, int K) {
    extern __shared__ uint16_t smx[];
    MMA_WCOORD
    const int m0 = blockIdx.x << 7;
    const int n0 = 0;
    const uint32_t uA = smem_u32(smx);
    const uint32_t uB = uA + AS_H * 2;
    ACC_ZERO

    const int arow = tid & 127, ahalf = tid >> 7;
    typename AL::Ctx ctx = al.prep(m0 + arow);
    const uint32_t dA = uA + (uint32_t)(arow * SROW + ahalf * 48) * 2;
    const bool bact = tid < 192;
    const int brow = bact ? (tid >> 1) : 0;
    const int bhalf = tid & 1;
    int brc = brow; if (brc >= Nt) brc = Nt - 1;
    const uint16_t* gB = (const uint16_t*)Bw + (size_t)brc * K + bhalf * 48;
    const uint32_t dB = uB + (uint32_t)(brow * SROW + bhalf * 48) * 2;

    const int nst = K / 96;
    for (int kc = 0; kc < nst; kc++) {
        const int kb = kc * 96;
        if (kc > 0) __syncthreads();
        if (bact) {
            #pragma unroll
            for (int j = 0; j < 6; j++) cpa16(dB + j * 16, gB + kb + j * 8);
        }
        CP_COMMIT();
        #pragma unroll
        for (int j = 0; j < 6; j++) {
            float4 v0 = al.load(ctx, kb + ahalf * 48 + j * 8);
            float4 v1 = al.load(ctx, kb + ahalf * 48 + j * 8 + 4);
            uint2 p0 = pack4h(v0), p1 = pack4h(v1);
            asm volatile("st.shared.v4.b32 [%0], {%1, %2, %3, %4};"
                :: "r"(dA + j * 16), "r"(p0.x), "r"(p0.y), "r"(p1.x), "r"(p1.y));
        }
        CP_WAIT0();
        __syncthreads();
        mma_stage96(uA, uB, aoff, boff, acc);
    }
    MMA_EPI(m0)
}

// ---------------- window attention -------------------------------------------
__global__ void __launch_bounds__(128) attn_kernel(const __half* __restrict__ qkv,
                                                   const float* __restrict__ rel,
                                                   __half* __restrict__ outp,
                                                   int shifted) {
    __shared__ float sq[2*784], sk[2*784], sv[2*784], srel[2*169];
    __shared__ int slbl[49];
    const int bw = blockIdx.x, h0 = blockIdx.y * 2;
    const int tid = threadIdx.x;

    for (int i = tid; i < 2 * 784; i += 128) {
        int hh = i / 784, idx = i - hh * 784;
        int h = h0 + hh;
        sq[i] = __half2float(qkv[(((size_t)(bw * 3 + 0) * 6 + h)) * 784 + idx]);
        sk[i] = __half2float(qkv[(((size_t)(bw * 3 + 1) * 6 + h)) * 784 + idx]);
        sv[i] = __half2float(qkv[(((size_t)(bw * 3 + 2) * 6 + h)) * 784 + idx]);
    }
    for (int i = tid; i < 2 * 169; i += 128) {
        int hh = i / 169, idx = i - hh * 169;
        srel[i] = rel[idx * 6 + h0 + hh];
    }
    if (tid < 49) {
        if (shifted) {
            int wy = (bw >> 4) & 15, wx = bw & 15;
            int yy = wy * 7 + tid / 7, xx = wx * 7 + tid % 7;
            int ry = (yy < 105) ? 0 : ((yy < 109) ? 1 : 2);
            int rx = (xx < 105) ? 0 : ((xx < 109) ? 1 : 2);
            slbl[tid] = ry * 3 + rx;
        } else slbl[tid] = 0;
    }
    __syncthreads();

    const int h2 = tid >> 6, n = tid & 63;
    if (n < 49) {
        const float* qh = sq + h2 * 784;
        const float* kh = sk + h2 * 784;
        const float* vh = sv + h2 * 784;
        const float* rh = srel + h2 * 169;
        const int iy = n / 7, ix = n - iy * 7;
        float4 q0 = *(const float4*)&qh[n*16+0];
        float4 q1 = *(const float4*)&qh[n*16+4];
        float4 q2 = *(const float4*)&qh[n*16+8];
        float4 q3 = *(const float4*)&qh[n*16+12];
        const int mylbl = slbl[n];
        float s[49];
        float mx = -1e30f;
        #pragma unroll
        for (int m = 0; m < 49; m++) {
            int jy = m / 7, jx = m - jy * 7;
            float4 k0 = *(const float4*)&kh[m*16+0];
            float4 k1 = *(const float4*)&kh[m*16+4];
            float4 k2 = *(const float4*)&kh[m*16+8];
            float4 k3 = *(const float4*)&kh[m*16+12];
            float d = q0.x*k0.x+q0.y*k0.y+q0.z*k0.z+q0.w*k0.w
                    + q1.x*k1.x+q1.y*k1.y+q1.z*k1.z+q1.w*k1.w
                    + q2.x*k2.x+q2.y*k2.y+q2.z*k2.z+q2.w*k2.w
                    + q3.x*k3.x+q3.y*k3.y+q3.z*k3.z+q3.w*k3.w;
            d += rh[(iy - jy + 6) * 13 + (ix - jx + 6)];
            if (shifted && slbl[m] != mylbl) d -= 100.f;
            s[m] = d;
            mx = fmaxf(mx, d);
        }
        float sum = 0.f;
        #pragma unroll
        for (int m = 0; m < 49; m++) {
            float e = __expf(s[m] - mx);
            s[m] = e;
            sum += e;
        }
        float inv = 1.f / sum;
        float o[16];
        #pragma unroll
        for (int d = 0; d < 16; d++) o[d] = 0.f;
        #pragma unroll
        for (int m = 0; m < 49; m++) {
            float p = s[m] * inv;
            float4 v0 = *(const float4*)&vh[m*16+0];
            float4 v1 = *(const float4*)&vh[m*16+4];
            float4 v2 = *(const float4*)&vh[m*16+8];
            float4 v3 = *(const float4*)&vh[m*16+12];
            o[0]+=p*v0.x; o[1]+=p*v0.y; o[2]+=p*v0.z; o[3]+=p*v0.w;
            o[4]+=p*v1.x; o[5]+=p*v1.y; o[6]+=p*v1.z; o[7]+=p*v1.w;
            o[8]+=p*v2.x; o[9]+=p*v2.y; o[10]+=p*v2.z; o[11]+=p*v2.w;
            o[12]+=p*v3.x; o[13]+=p*v3.y; o[14]+=p*v3.z; o[15]+=p*v3.w;
        }
        uint32_t u[8];
        #pragma unroll
        for (int d = 0; d < 8; d++) u[d] = pack2h(o[2*d], o[2*d+1]);
        size_t o0 = ((size_t)bw * 49 + n) * C2 + (h0 + h2) * 16;
        ((uint4*)(outp + o0))[0] = make_uint4(u[0], u[1], u[2], u[3]);
        ((uint4*)(outp + o0))[1] = make_uint4(u[4], u[5], u[6], u[7]);
    }
}

// ---------------- launch -----------------------------------------------------
extern "C" void kernel_launch(void* const* d_in, const int* in_sizes, int n_in,
                              void* d_out, int out_size) {
    (void)in_sizes; (void)n_in; (void)out_size;
    const float* x     = (const float*)d_in[0];
    const float* up_w  = (const float*)d_in[1];
    const float* up_b  = (const float*)d_in[2];
    const float* bn_g  = (const float*)d_in[3];
    const float* bn_b  = (const float*)d_in[4];
    const float* bn_m  = (const float*)d_in[5];
    const float* bn_v  = (const float*)d_in[6];
    const float* n1g   = (const float*)d_in[7];
    const float* n1b   = (const float*)d_in[8];
    const float* qkvw  = (const float*)d_in[9];
    const float* qkvb  = (const float*)d_in[10];
    const float* projw = (const float*)d_in[11];
    const float* projb = (const float*)d_in[12];
    const float* rel   = (const float*)d_in[13];
    const float* n2g   = (const float*)d_in[14];
    const float* n2b   = (const float*)d_in[15];
    const float* f1w   = (const float*)d_in[16];
    const float* f1b   = (const float*)d_in[17];
    const float* f2w   = (const float*)d_in[18];
    const float* f2b   = (const float*)d_in[19];
    const float* outw  = (const float*)d_in[20];
    const float* outb  = (const float*)d_in[21];
    float* out = (float*)d_out;

    float *bX, *scl, *sft;
    __half *bQ, *bW, *bA, *bH, *wf;
    cudaGetSymbolAddress((void**)&bX, d_bufX);
    cudaGetSymbolAddress((void**)&bQ, d_bufQ);
    cudaGetSymbolAddress((void**)&bW, d_bW);
    cudaGetSymbolAddress((void**)&bA, d_bA);
    cudaGetSymbolAddress((void**)&bH, d_bH);
    cudaGetSymbolAddress((void**)&wf, d_wf);
    cudaGetSymbolAddress((void**)&scl, d_cscale);
    cudaGetSymbolAddress((void**)&sft, d_cshift);

    cudaFuncSetAttribute(mma_gemm_ps<StQKV>,  cudaFuncAttributeMaxDynamicSharedMemorySize, SMEM_PS);
    cudaFuncSetAttribute(mma_gemm_ps<StGelu>, cudaFuncAttributeMaxDynamicSharedMemorySize, SMEM_PS);
    cudaFuncSetAttribute(mma_gemm_pf<0>,      cudaFuncAttributeMaxDynamicSharedMemorySize, SMEM_F);
    cudaFuncSetAttribute(mma_gemm_pf<1>,      cudaFuncAttributeMaxDynamicSharedMemorySize, SMEM_F);
    cudaFuncSetAttribute(conv_ln_kernel,      cudaFuncAttributeMaxDynamicSharedMemorySize, SMEM_F);

    prep_conv<<<64, 256>>>(up_w, up_b, bn_g, bn_b, bn_m, bn_v);
    prep_w<<<221, 512>>>(qkvw, projw, f1w, f2w, outw);

    {   // conv + BN/ReLU + LN1(shift0): writes bX and bW
        ALConv al; al.in = x;
        conv_ln_kernel<<<dim3(196, 1, 4), 256, SMEM_F>>>(al, wf + OFF_WC, 96 * 768,
                                                         bX, bW, scl, sft, n1g, n1b);
    }

    for (int i = 0; i < 2; i++) {
        int sh = i ? 3 : 0;

        { StQKV st; st.out = bQ; st.bias = qkvb + i * 288;
          mma_gemm_ps<<<dim3(98, 3), 256, SMEM_PS>>>(bW, st,
              wf + OFF_QKV + (size_t)i * 27648, 288, 784); }

        attn_kernel<<<dim3(2048, 3), 128>>>(bQ, rel + (size_t)i * 169 * 6, bA, sh);

        // proj + residual + LN2 -> bW
        mma_gemm_pf<0><<<784, 256, SMEM_F>>>(bA, wf + OFF_PROJ + (size_t)i * 9216, 96,
                                             bX, bW, projb + i * 96,
                                             n2g + i * 96, n2b + i * 96, sh);

        { StGelu st; st.outp = bH; st.bias = f1b + i * HID;
          mma_gemm_ps<<<dim3(74, 4), 256, SMEM_PS>>>(bW, st,
              wf + OFF_F1 + (size_t)i * 36864, HID, 784); }

        if (i == 0) {
            // FC2 + residual + LN1(shift3) -> bW  (feeds block-1 QKV)
            mma_gemm_pf<1><<<784, 256, SMEM_F>>>(bH, wf + OFF_F2, 384,
                                                 bX, bW, f2b,
                                                 n1g + 96, n1b + 96, 3);
        } else {
            StFC2 st; st.out = bX; st.bias = f2b + 96;
            mma_gemm_p<<<dim3(784, 1), 256, SMEM_BYTES>>>(bH, st,
                wf + OFF_F2 + 36864, 96, 384);
        }
    }

    { ALDirect al; al.A = bX; al.K = 96;
      StOut st; st.out = out; st.bias = outb;
      mma_gemm_f<<<dim3(784, 1), 256, SMEM_BYTES>>>(al, st, wf + OFF_OUT, 48, 96); }
}